// round 12
// baseline (speedup 1.0000x reference)
#include <cuda_runtime.h>
#include <cuda_bf16.h>
#include <math.h>
#include <stdint.h>

#define NN 50000
#define EE 800000
#define XD 192
#define MPAD 50048
#define KB 768          // split-K: [hi | hi | lo] x 256

// ---------------- scratch ----------------
static __device__ __nv_bfloat16 g_Abig[(size_t)MPAD * KB];   // A' splits
static __device__ __nv_bfloat16 g_Wbig[768 * KB];            // W' gemm1 (ll|lr|res)
static __device__ __nv_bfloat16 g_W2big[256 * KB];            // W' gemm2 (proj)
static __device__ float g_B[768];
static __device__ float g_nuv[NN * 2];
static __device__ float g_xl[(size_t)NN * 256];              // x_l dense
static __device__ float g_xri[(size_t)NN * 512];             // x_r | identity
static __device__ float g_logits[EE * 4];                    // bucket-ordered
static __device__ float4 g_bgeo[EE];                         // (rx, ry, dist, src-bits)
static __device__ int   g_deg[NN];
static __device__ int   g_cur[NN];
static __device__ int   g_off[NN + 1];
static __device__ int   g_bkt[EE];
static __device__ int   g_bsum[256];

__device__ __forceinline__ float wsum(float v) {
#pragma unroll
    for (int o = 16; o > 0; o >>= 1) v += __shfl_xor_sync(0xffffffffu, v, o);
    return v;
}

__device__ __forceinline__ uint32_t pk2(float a, float b, float* ra, float* rb) {
    __nv_bfloat16 ha = __float2bfloat16(a), hb = __float2bfloat16(b);
    *ra = a - __bfloat162float(ha);
    *rb = b - __bfloat162float(hb);
    return (uint32_t)__bfloat16_as_ushort(ha) | ((uint32_t)__bfloat16_as_ushort(hb) << 16);
}
__device__ __forceinline__ uint32_t pk2n(float a, float b) {
    return (uint32_t)__bfloat16_as_ushort(__float2bfloat16(a)) |
           ((uint32_t)__bfloat16_as_ushort(__float2bfloat16(b)) << 16);
}

__device__ __forceinline__ uint32_t s2u(const void* p) {
    uint32_t a;
    asm("{ .reg .u64 t; cvta.to.shared.u64 t, %1; cvt.u32.u64 %0, t; }" : "=r"(a) : "l"(p));
    return a;
}

// ---------------- init ----------------
__global__ void k_init() {
    int t = blockIdx.x * blockDim.x + threadIdx.x;
    if (t < NN) { g_deg[t] = 0; g_cur[t] = 0; }
}

// ---------------- pos encoder + A' assembly (1 warp / node, vectorized stores) ---------
__global__ void __launch_bounds__(256) k_node(const float* __restrict__ x,
                       const float* __restrict__ kpts,
                       const float* __restrict__ pts3d,
                       const float* __restrict__ w1, const float* __restrict__ b1,
                       const float* __restrict__ g1, const float* __restrict__ bn1,
                       const float* __restrict__ w2, const float* __restrict__ b2,
                       const float* __restrict__ g2, const float* __restrict__ bn2) {
    int gw = (blockIdx.x * blockDim.x + threadIdx.x) >> 5;
    int lane = threadIdx.x & 31;
    int w = threadIdx.x >> 5;
    if (gw >= NN) return;
    int n = gw;

    __shared__ float rowbuf[8][256];
    float* row = rowbuf[w];

    float nu = kpts[n * 2]     * (1.0f / 1216.0f);
    float nv = kpts[n * 2 + 1] * (1.0f / 352.0f);
    float dep = pts3d[n * 3 + 2];
    dep = fminf(fmaxf(dep, 0.1f), 100.0f);

    float h = nu * w1[lane * 3] + nv * w1[lane * 3 + 1] + dep * w1[lane * 3 + 2] + b1[lane];
    float mu = wsum(h) * (1.0f / 32.0f);
    float d = h - mu;
    float var = wsum(d * d) * (1.0f / 32.0f);
    float y = d * rsqrtf(var + 1e-5f) * g1[lane] + bn1[lane];
    y = y / (1.0f + __expf(-y));

    row[lane] = y;
    __syncwarp();

    float o0 = b2[lane], o1 = b2[lane + 32];
#pragma unroll
    for (int j = 0; j < 32; j++) {
        float hv = row[j];
        o0 += hv * w2[lane * 32 + j];
        o1 += hv * w2[(lane + 32) * 32 + j];
    }
    float mean = wsum(o0 + o1) * (1.0f / 64.0f);
    float d0 = o0 - mean, d1 = o1 - mean;
    float v2 = wsum(d0 * d0 + d1 * d1) * (1.0f / 64.0f);
    float r = rsqrtf(v2 + 1e-5f);
    float p0 = d0 * r * g2[lane] + bn2[lane];
    float p1 = d1 * r * g2[lane + 32] + bn2[lane + 32];
    __syncwarp();

    // assemble full 256-float row in smem
#pragma unroll
    for (int i = 0; i < 6; i++) row[lane + i * 32] = x[n * XD + lane + i * 32];
    row[192 + lane] = p0;
    row[224 + lane] = p1;
    __syncwarp();

    // each lane: 8 consecutive cols -> 3 x STG.128
    float v[8], rl[8];
#pragma unroll
    for (int k = 0; k < 8; k++) v[k] = row[lane * 8 + k];
    uint4 hiq, loq;
    hiq.x = pk2(v[0], v[1], &rl[0], &rl[1]);
    hiq.y = pk2(v[2], v[3], &rl[2], &rl[3]);
    hiq.z = pk2(v[4], v[5], &rl[4], &rl[5]);
    hiq.w = pk2(v[6], v[7], &rl[6], &rl[7]);
    loq.x = pk2n(rl[0], rl[1]);
    loq.y = pk2n(rl[2], rl[3]);
    loq.z = pk2n(rl[4], rl[5]);
    loq.w = pk2n(rl[6], rl[7]);

    size_t base = (size_t)n * KB + lane * 8;
    *reinterpret_cast<uint4*>(&g_Abig[base])       = hiq;
    *reinterpret_cast<uint4*>(&g_Abig[base + 256]) = hiq;
    *reinterpret_cast<uint4*>(&g_Abig[base + 512]) = loq;

    if (lane == 0) { g_nuv[2 * n] = nu; g_nuv[2 * n + 1] = nv; }
}

// ---------------- weight splits ----------------
__global__ void k_concat(const float* ll, const float* lr, const float* rw,
                         const float* lb, const float* rb, const float* resb) {
    int t = blockIdx.x * blockDim.x + threadIdx.x;
    if (t < 196608) {
        float v;
        if (t < 65536)       v = ll[t];
        else if (t < 131072) v = lr[t - 65536];
        else                 v = rw[t - 131072];
        int row = t >> 8, col = t & 255;
        __nv_bfloat16 h = __float2bfloat16(v);
        __nv_bfloat16 l = __float2bfloat16(v - __bfloat162float(h));
        g_Wbig[row * KB + col]       = h;
        g_Wbig[row * KB + 256 + col] = l;
        g_Wbig[row * KB + 512 + col] = h;
    }
    if (t < 256)       g_B[t] = lb[t];
    else if (t < 512)  g_B[t] = rb[t - 256];
    else if (t < 768)  g_B[t] = resb[t - 512];
}

__global__ void k_splitW2(const float* pw) {
    int t = blockIdx.x * blockDim.x + threadIdx.x;
    if (t < 65536) {
        float v = pw[t];
        int row = t >> 8, col = t & 255;
        __nv_bfloat16 h = __float2bfloat16(v);
        __nv_bfloat16 l = __float2bfloat16(v - __bfloat162float(h));
        g_W2big[row * KB + col]       = h;
        g_W2big[row * KB + 256 + col] = l;
        g_W2big[row * KB + 512 + col] = h;
    }
}

// -------- mma.sync bf16 GEMM: C[M,*] = A'[M,768] * W'[Ncols,768]^T + bias --------
#define SSTRIDE 72
#define ABYTES  18432
__global__ void __launch_bounds__(256, 2) k_mgemm(const __nv_bfloat16* __restrict__ A,
                                                  const __nv_bfloat16* __restrict__ Bw,
                                                  const float* __restrict__ bias,
                                                  float* __restrict__ C, int M, int ldc) {
    extern __shared__ __align__(16) char smem[];
    const int tid = threadIdx.x, wid = tid >> 5, lane = tid & 31;
    const int mBase = blockIdx.y * 128;
    const int nBase = blockIdx.x * 128;
    const uint32_t sb = s2u(smem);
    const uint32_t sA[2] = {sb, sb + ABYTES};
    const uint32_t sB[2] = {sb + 2 * ABYTES, sb + 3 * ABYTES};

    const int wm = wid & 1;
    const int wn = wid >> 1;
    const int grp = lane >> 3;
    const int l8 = lane & 7;
    const int ldRow = tid >> 3;
    const int ldSeg = tid & 7;

    float c[4][4][4];
#pragma unroll
    for (int mt = 0; mt < 4; mt++)
#pragma unroll
        for (int nt = 0; nt < 4; nt++)
#pragma unroll
            for (int q = 0; q < 4; q++) c[mt][nt][q] = 0.0f;

    uint32_t aAddr[4];
#pragma unroll
    for (int mt = 0; mt < 4; mt++) {
        int row = wm * 64 + mt * 16 + (grp & 1) * 8 + l8;
        aAddr[mt] = (uint32_t)(row * (SSTRIDE * 2) + (grp >> 1) * 16);
    }
    uint32_t bAddr[2];
#pragma unroll
    for (int p = 0; p < 2; p++) {
        int nrow = wn * 32 + (2 * p + (grp >> 1)) * 8 + l8;
        bAddr[p] = (uint32_t)(nrow * (SSTRIDE * 2) + (grp & 1) * 16);
    }

    {
        const int b = 0, ch = 0;
#pragma unroll
        for (int i = 0; i < 4; i++) {
            int row = ldRow + i * 32;
            uint32_t sa = sA[b] + (uint32_t)(row * (SSTRIDE * 2) + ldSeg * 16);
            const __nv_bfloat16* ga = A + (size_t)(mBase + row) * KB + ch * 64 + ldSeg * 8;
            asm volatile("cp.async.cg.shared.global [%0], [%1], 16;" :: "r"(sa), "l"(ga));
            uint32_t sbb = sB[b] + (uint32_t)(row * (SSTRIDE * 2) + ldSeg * 16);
            const __nv_bfloat16* gb = Bw + (size_t)(nBase + row) * KB + ch * 64 + ldSeg * 8;
            asm volatile("cp.async.cg.shared.global [%0], [%1], 16;" :: "r"(sbb), "l"(gb));
        }
        asm volatile("cp.async.commit_group;" ::: "memory");
    }

    for (int ch = 0; ch < 12; ch++) {
        int b = ch & 1;
        if (ch + 1 < 12) {
            int nb = (ch + 1) & 1;
#pragma unroll
            for (int i = 0; i < 4; i++) {
                int row = ldRow + i * 32;
                uint32_t sa = sA[nb] + (uint32_t)(row * (SSTRIDE * 2) + ldSeg * 16);
                const __nv_bfloat16* ga = A + (size_t)(mBase + row) * KB + (ch + 1) * 64 + ldSeg * 8;
                asm volatile("cp.async.cg.shared.global [%0], [%1], 16;" :: "r"(sa), "l"(ga));
                uint32_t sbb = sB[nb] + (uint32_t)(row * (SSTRIDE * 2) + ldSeg * 16);
                const __nv_bfloat16* gb = Bw + (size_t)(nBase + row) * KB + (ch + 1) * 64 + ldSeg * 8;
                asm volatile("cp.async.cg.shared.global [%0], [%1], 16;" :: "r"(sbb), "l"(gb));
            }
            asm volatile("cp.async.commit_group;" ::: "memory");
            asm volatile("cp.async.wait_group 1;" ::: "memory");
        } else {
            asm volatile("cp.async.wait_group 0;" ::: "memory");
        }
        __syncthreads();

#pragma unroll
        for (int ks = 0; ks < 4; ks++) {
            uint32_t a[4][4], bb[4][2];
#pragma unroll
            for (int mt = 0; mt < 4; mt++) {
                uint32_t addr = sA[b] + aAddr[mt] + ks * 32;
                asm volatile("ldmatrix.sync.aligned.m8n8.x4.shared.b16 {%0,%1,%2,%3}, [%4];"
                             : "=r"(a[mt][0]), "=r"(a[mt][1]), "=r"(a[mt][2]), "=r"(a[mt][3])
                             : "r"(addr));
            }
#pragma unroll
            for (int p = 0; p < 2; p++) {
                uint32_t addr = sB[b] + bAddr[p] + ks * 32;
                asm volatile("ldmatrix.sync.aligned.m8n8.x4.shared.b16 {%0,%1,%2,%3}, [%4];"
                             : "=r"(bb[2 * p][0]), "=r"(bb[2 * p][1]),
                               "=r"(bb[2 * p + 1][0]), "=r"(bb[2 * p + 1][1])
                             : "r"(addr));
            }
#pragma unroll
            for (int mt = 0; mt < 4; mt++)
#pragma unroll
                for (int nt = 0; nt < 4; nt++) {
                    asm volatile(
                        "mma.sync.aligned.m16n8k16.row.col.f32.bf16.bf16.f32 "
                        "{%0,%1,%2,%3}, {%4,%5,%6,%7}, {%8,%9}, {%0,%1,%2,%3};"
                        : "+f"(c[mt][nt][0]), "+f"(c[mt][nt][1]),
                          "+f"(c[mt][nt][2]), "+f"(c[mt][nt][3])
                        : "r"(a[mt][0]), "r"(a[mt][1]), "r"(a[mt][2]), "r"(a[mt][3]),
                          "r"(bb[nt][0]), "r"(bb[nt][1]));
                }
        }
        __syncthreads();
    }

#pragma unroll
    for (int mt = 0; mt < 4; mt++) {
        int r0 = mBase + wm * 64 + mt * 16 + (lane >> 2);
        int r1 = r0 + 8;
#pragma unroll
        for (int nt = 0; nt < 4; nt++) {
            int col = nBase + wn * 32 + nt * 8 + (lane & 3) * 2;
            float b0 = bias[col], b1 = bias[col + 1];
            if (r0 < M) {
                float2 v = make_float2(c[mt][nt][0] + b0, c[mt][nt][1] + b1);
                *reinterpret_cast<float2*>(C + (size_t)r0 * ldc + col) = v;
            }
            if (r1 < M) {
                float2 v = make_float2(c[mt][nt][2] + b0, c[mt][nt][3] + b1);
                *reinterpret_cast<float2*>(C + (size_t)r1 * ldc + col) = v;
            }
        }
    }
}

// gemm1 wrapper: cols [0,256) -> g_xl (ldc 256), cols [256,768) -> g_xri (ldc 512)
__global__ void __launch_bounds__(256, 2) k_mgemm1(const __nv_bfloat16* __restrict__ A,
                                                   const __nv_bfloat16* __restrict__ Bw,
                                                   const float* __restrict__ bias,
                                                   float* __restrict__ Cxl,
                                                   float* __restrict__ Cxri, int M) {
    extern __shared__ __align__(16) char smem[];
    const int tid = threadIdx.x, wid = tid >> 5, lane = tid & 31;
    const int mBase = blockIdx.y * 128;
    const int bx = blockIdx.x;
    float* C; int ldc, nBase;
    if (bx < 2) { C = Cxl; ldc = 256; nBase = bx * 128; }
    else        { C = Cxri; ldc = 512; nBase = (bx - 2) * 128; }
    const int nBaseW = bx * 128;
    const uint32_t sb = s2u(smem);
    const uint32_t sA[2] = {sb, sb + ABYTES};
    const uint32_t sB[2] = {sb + 2 * ABYTES, sb + 3 * ABYTES};

    const int wm = wid & 1;
    const int wn = wid >> 1;
    const int grp = lane >> 3;
    const int l8 = lane & 7;
    const int ldRow = tid >> 3;
    const int ldSeg = tid & 7;

    float c[4][4][4];
#pragma unroll
    for (int mt = 0; mt < 4; mt++)
#pragma unroll
        for (int nt = 0; nt < 4; nt++)
#pragma unroll
            for (int q = 0; q < 4; q++) c[mt][nt][q] = 0.0f;

    uint32_t aAddr[4];
#pragma unroll
    for (int mt = 0; mt < 4; mt++) {
        int row = wm * 64 + mt * 16 + (grp & 1) * 8 + l8;
        aAddr[mt] = (uint32_t)(row * (SSTRIDE * 2) + (grp >> 1) * 16);
    }
    uint32_t bAddr[2];
#pragma unroll
    for (int p = 0; p < 2; p++) {
        int nrow = wn * 32 + (2 * p + (grp >> 1)) * 8 + l8;
        bAddr[p] = (uint32_t)(nrow * (SSTRIDE * 2) + (grp & 1) * 16);
    }

    {
        const int b = 0, ch = 0;
#pragma unroll
        for (int i = 0; i < 4; i++) {
            int row = ldRow + i * 32;
            uint32_t sa = sA[b] + (uint32_t)(row * (SSTRIDE * 2) + ldSeg * 16);
            const __nv_bfloat16* ga = A + (size_t)(mBase + row) * KB + ch * 64 + ldSeg * 8;
            asm volatile("cp.async.cg.shared.global [%0], [%1], 16;" :: "r"(sa), "l"(ga));
            uint32_t sbb = sB[b] + (uint32_t)(row * (SSTRIDE * 2) + ldSeg * 16);
            const __nv_bfloat16* gb = Bw + (size_t)(nBaseW + row) * KB + ch * 64 + ldSeg * 8;
            asm volatile("cp.async.cg.shared.global [%0], [%1], 16;" :: "r"(sbb), "l"(gb));
        }
        asm volatile("cp.async.commit_group;" ::: "memory");
    }

    for (int ch = 0; ch < 12; ch++) {
        int b = ch & 1;
        if (ch + 1 < 12) {
            int nb = (ch + 1) & 1;
#pragma unroll
            for (int i = 0; i < 4; i++) {
                int row = ldRow + i * 32;
                uint32_t sa = sA[nb] + (uint32_t)(row * (SSTRIDE * 2) + ldSeg * 16);
                const __nv_bfloat16* ga = A + (size_t)(mBase + row) * KB + (ch + 1) * 64 + ldSeg * 8;
                asm volatile("cp.async.cg.shared.global [%0], [%1], 16;" :: "r"(sa), "l"(ga));
                uint32_t sbb = sB[nb] + (uint32_t)(row * (SSTRIDE * 2) + ldSeg * 16);
                const __nv_bfloat16* gb = Bw + (size_t)(nBaseW + row) * KB + (ch + 1) * 64 + ldSeg * 8;
                asm volatile("cp.async.cg.shared.global [%0], [%1], 16;" :: "r"(sbb), "l"(gb));
            }
            asm volatile("cp.async.commit_group;" ::: "memory");
            asm volatile("cp.async.wait_group 1;" ::: "memory");
        } else {
            asm volatile("cp.async.wait_group 0;" ::: "memory");
        }
        __syncthreads();

#pragma unroll
        for (int ks = 0; ks < 4; ks++) {
            uint32_t a[4][4], bb[4][2];
#pragma unroll
            for (int mt = 0; mt < 4; mt++) {
                uint32_t addr = sA[b] + aAddr[mt] + ks * 32;
                asm volatile("ldmatrix.sync.aligned.m8n8.x4.shared.b16 {%0,%1,%2,%3}, [%4];"
                             : "=r"(a[mt][0]), "=r"(a[mt][1]), "=r"(a[mt][2]), "=r"(a[mt][3])
                             : "r"(addr));
            }
#pragma unroll
            for (int p = 0; p < 2; p++) {
                uint32_t addr = sB[b] + bAddr[p] + ks * 32;
                asm volatile("ldmatrix.sync.aligned.m8n8.x4.shared.b16 {%0,%1,%2,%3}, [%4];"
                             : "=r"(bb[2 * p][0]), "=r"(bb[2 * p][1]),
                               "=r"(bb[2 * p + 1][0]), "=r"(bb[2 * p + 1][1])
                             : "r"(addr));
            }
#pragma unroll
            for (int mt = 0; mt < 4; mt++)
#pragma unroll
                for (int nt = 0; nt < 4; nt++) {
                    asm volatile(
                        "mma.sync.aligned.m16n8k16.row.col.f32.bf16.bf16.f32 "
                        "{%0,%1,%2,%3}, {%4,%5,%6,%7}, {%8,%9}, {%0,%1,%2,%3};"
                        : "+f"(c[mt][nt][0]), "+f"(c[mt][nt][1]),
                          "+f"(c[mt][nt][2]), "+f"(c[mt][nt][3])
                        : "r"(a[mt][0]), "r"(a[mt][1]), "r"(a[mt][2]), "r"(a[mt][3]),
                          "r"(bb[nt][0]), "r"(bb[nt][1]));
                }
        }
        __syncthreads();
    }

#pragma unroll
    for (int mt = 0; mt < 4; mt++) {
        int r0 = mBase + wm * 64 + mt * 16 + (lane >> 2);
        int r1 = r0 + 8;
#pragma unroll
        for (int nt = 0; nt < 4; nt++) {
            int colW = nBaseW + wn * 32 + nt * 8 + (lane & 3) * 2;
            int col = nBase + wn * 32 + nt * 8 + (lane & 3) * 2;
            float b0 = bias[colW], b1 = bias[colW + 1];
            if (r0 < M) {
                float2 v = make_float2(c[mt][nt][0] + b0, c[mt][nt][1] + b1);
                *reinterpret_cast<float2*>(C + (size_t)r0 * ldc + col) = v;
            }
            if (r1 < M) {
                float2 v = make_float2(c[mt][nt][2] + b0, c[mt][nt][3] + b1);
                *reinterpret_cast<float2*>(C + (size_t)r1 * ldc + col) = v;
            }
        }
    }
}

// ---------------- CSR build ----------------
__global__ void k_hist(const int* __restrict__ ei) {
    int t = blockIdx.x * blockDim.x + threadIdx.x;
    if (t < EE) atomicAdd(&g_deg[ei[EE + t]], 1);
}

__global__ void k_scan1() {
    __shared__ int sh[256];
    int b = blockIdx.x, tid = threadIdx.x;
    int i = b * 256 + tid;
    int v = (i < NN) ? g_deg[i] : 0;
    sh[tid] = v;
    __syncthreads();
    for (int o = 1; o < 256; o <<= 1) {
        int t = (tid >= o) ? sh[tid - o] : 0;
        __syncthreads();
        sh[tid] += t;
        __syncthreads();
    }
    if (i < NN) g_off[i] = sh[tid] - v;
    if (tid == 255) g_bsum[b] = sh[255];
}

__global__ void k_scan2() {
    __shared__ int sh[256];
    int tid = threadIdx.x;
    int v = (tid < 196) ? g_bsum[tid] : 0;
    sh[tid] = v;
    __syncthreads();
    for (int o = 1; o < 256; o <<= 1) {
        int t = (tid >= o) ? sh[tid - o] : 0;
        __syncthreads();
        sh[tid] += t;
        __syncthreads();
    }
    g_bsum[tid] = sh[tid] - v;
}

__global__ void k_scan3() {
    int i = blockIdx.x * 256 + threadIdx.x;
    if (i < NN) g_off[i] += g_bsum[blockIdx.x];
    if (i == 0) g_off[NN] = EE;
}

// bucket fill + geometry precompute + edge_attr output
__global__ void k_bucket(const int* __restrict__ ei, float* __restrict__ outE) {
    int t = blockIdx.x * blockDim.x + threadIdx.x;
    if (t < EE) {
        int s = ei[t];
        int d = ei[EE + t];
        int p = atomicAdd(&g_cur[d], 1);
        int pos = g_off[d] + p;
        g_bkt[pos] = t;
        const float2* nuv2 = (const float2*)g_nuv;
        float2 nd = nuv2[d], ns = nuv2[s];
        float rx = nd.x - ns.x;
        float ry = nd.y - ns.y;
        float dd = sqrtf(rx * rx + ry * ry);
        g_bgeo[pos] = make_float4(rx, ry, dd, __int_as_float(s));
        outE[(size_t)t * 3]     = rx;
        outE[(size_t)t * 3 + 1] = ry;
        outE[(size_t)t * 3 + 2] = dd;
    }
}

// ------- per-node attention: 2 warps/node, dual-state softmax, alpha, LN, SiLU -------
__global__ void __launch_bounds__(256) k_agg(const float* __restrict__ att,
                      const float* __restrict__ We, const float* __restrict__ cb,
                      const float* __restrict__ ng, const float* __restrict__ nb,
                      float* __restrict__ outA) {
    int gw = (blockIdx.x * blockDim.x + threadIdx.x) >> 5;
    int lane = threadIdx.x & 31;
    int wib = (threadIdx.x >> 5);
    int n = gw >> 1;
    int w = gw & 1;

    int fbase = w * 128 + lane * 4;
    float attv[4], we0[4], we1[4], we2[4], xr[4], accA[4], accB[4];
#pragma unroll
    for (int k = 0; k < 4; k++) {
        int j = fbase + k;
        attv[k] = att[j];
        we0[k] = We[j * 3]; we1[k] = We[j * 3 + 1]; we2[k] = We[j * 3 + 2];
        accA[k] = 0.0f; accB[k] = 0.0f;
    }
    {
        float4 a = ((const float4*)&g_xri[(size_t)n * 512 + w * 128])[lane];
        xr[0] = a.x; xr[1] = a.y; xr[2] = a.z; xr[3] = a.w;
    }
    float mA = -3.0e38f, sA = 0.0f, mB = -3.0e38f, sB = 0.0f;
    int beg = g_off[n], end = g_off[n + 1];
    int hsel = w * 2 + (lane >> 4);

    int i = beg;
    float4 gA = make_float4(0.f,0.f,0.f,0.f), gB = gA, xA = gA, xB = gA;
    if (i + 1 < end) {
        gA = g_bgeo[i]; gB = g_bgeo[i + 1];
        xA = ((const float4*)&g_xl[(size_t)__float_as_int(gA.w) * 256 + w * 128])[lane];
        xB = ((const float4*)&g_xl[(size_t)__float_as_int(gB.w) * 256 + w * 128])[lane];
    }
    while (i + 1 < end) {
        float4 cgA = gA, cgB = gB;
        float xlA[4] = {xA.x, xA.y, xA.z, xA.w};
        float xlB[4] = {xB.x, xB.y, xB.z, xB.w};
        int ni = i + 2;
        if (ni + 1 < end) {
            gA = g_bgeo[ni]; gB = g_bgeo[ni + 1];
            xA = ((const float4*)&g_xl[(size_t)__float_as_int(gA.w) * 256 + w * 128])[lane];
            xB = ((const float4*)&g_xl[(size_t)__float_as_int(gB.w) * 256 + w * 128])[lane];
        }
        float ppA = 0.0f, ppB = 0.0f;
#pragma unroll
        for (int k = 0; k < 4; k++) {
            float zA = xlA[k] + xr[k] + (cgA.x * we0[k] + cgA.y * we1[k] + cgA.z * we2[k]);
            float zB = xlB[k] + xr[k] + (cgB.x * we0[k] + cgB.y * we1[k] + cgB.z * we2[k]);
            zA = (zA > 0.0f) ? zA : 0.2f * zA;
            zB = (zB > 0.0f) ? zB : 0.2f * zB;
            ppA += zA * attv[k];
            ppB += zB * attv[k];
        }
#pragma unroll
        for (int o = 1; o < 16; o <<= 1) {
            ppA += __shfl_xor_sync(0xffffffffu, ppA, o);
            ppB += __shfl_xor_sync(0xffffffffu, ppB, o);
        }
        if ((lane & 15) == 0) {
            g_logits[i * 4 + hsel]       = ppA;
            g_logits[(i + 1) * 4 + hsel] = ppB;
        }
        {
            float mn = fmaxf(mA, ppA);
            float sc = __expf(mA - mn);
            float p = __expf(ppA - mn);
            sA = sA * sc + p;
            mA = mn;
#pragma unroll
            for (int k = 0; k < 4; k++) accA[k] = accA[k] * sc + p * xlA[k];
        }
        {
            float mn = fmaxf(mB, ppB);
            float sc = __expf(mB - mn);
            float p = __expf(ppB - mn);
            sB = sB * sc + p;
            mB = mn;
#pragma unroll
            for (int k = 0; k < 4; k++) accB[k] = accB[k] * sc + p * xlB[k];
        }
        i = ni;
    }
    if (i < end) {
        float4 g = g_bgeo[i];
        float4 xa = ((const float4*)&g_xl[(size_t)__float_as_int(g.w) * 256 + w * 128])[lane];
        float xl[4] = {xa.x, xa.y, xa.z, xa.w};
        float pp = 0.0f;
#pragma unroll
        for (int k = 0; k < 4; k++) {
            float z = xl[k] + xr[k] + (g.x * we0[k] + g.y * we1[k] + g.z * we2[k]);
            z = (z > 0.0f) ? z : 0.2f * z;
            pp += z * attv[k];
        }
#pragma unroll
        for (int o = 1; o < 16; o <<= 1) pp += __shfl_xor_sync(0xffffffffu, pp, o);
        if ((lane & 15) == 0) g_logits[i * 4 + hsel] = pp;
        float mn = fmaxf(mA, pp);
        float sc = __expf(mA - mn);
        float p = __expf(pp - mn);
        sA = sA * sc + p;
        mA = mn;
#pragma unroll
        for (int k = 0; k < 4; k++) accA[k] = accA[k] * sc + p * xl[k];
    }

    float m = fmaxf(mA, mB);
    float eA = __expf(mA - m), eB = __expf(mB - m);
    float s = sA * eA + sB * eB;
    float acc[4];
#pragma unroll
    for (int k = 0; k < 4; k++) acc[k] = accA[k] * eA + accB[k] * eB;

    __threadfence_block();
    __syncwarp();
    {
        float mh0 = __shfl_sync(0xffffffffu, m, 0);
        float mh1 = __shfl_sync(0xffffffffu, m, 16);
        float ih0 = 1.0f / (__shfl_sync(0xffffffffu, s, 0)  + 1e-16f);
        float ih1 = 1.0f / (__shfl_sync(0xffffffffu, s, 16) + 1e-16f);
        int deg = end - beg;
        for (int j = lane; j < deg; j += 32) {
            int pos = beg + j;
            float2 lg = *(const float2*)&g_logits[(size_t)pos * 4 + w * 2];
            int e = g_bkt[pos];
            float2 av;
            av.x = __expf(lg.x - mh0) * ih0;
            av.y = __expf(lg.y - mh1) * ih1;
            *(float2*)&outA[(size_t)e * 4 + w * 2] = av;
        }
    }

    float inv = (end > beg) ? (1.0f / s) : 0.0f;
    float o[4];
#pragma unroll
    for (int k = 0; k < 4; k++) o[k] = acc[k] * inv + cb[fbase + k];

    __shared__ float sSum[8], sVar[8];
    float ps = o[0] + o[1] + o[2] + o[3];
    ps = wsum(ps);
    if (lane == 0) sSum[wib] = ps;
    __syncthreads();
    float mean = (sSum[wib ^ 1] + ps) * (1.0f / 256.0f);
    float pv = 0.0f;
#pragma unroll
    for (int k = 0; k < 4; k++) { float d = o[k] - mean; pv += d * d; }
    pv = wsum(pv);
    if (lane == 0) sVar[wib] = pv;
    __syncthreads();
    float var = (sVar[wib ^ 1] + pv) * (1.0f / 256.0f);
    float r = rsqrtf(var + 1e-5f);

    float4 iv = ((const float4*)&g_xri[(size_t)n * 512 + 256 + w * 128])[lane];
    float idv[4] = {iv.x, iv.y, iv.z, iv.w};
    float y[4];
#pragma unroll
    for (int k = 0; k < 4; k++) {
        int j = fbase + k;
        float t = (o[k] - mean) * r * ng[j] + nb[j] + idv[k];
        y[k] = t / (1.0f + __expf(-t));
    }
    // vectorized split stores: 3 x STG.64 (4 consecutive cols per lane)
    float rl[4];
    uint2 hiv, lov;
    hiv.x = pk2(y[0], y[1], &rl[0], &rl[1]);
    hiv.y = pk2(y[2], y[3], &rl[2], &rl[3]);
    lov.x = pk2n(rl[0], rl[1]);
    lov.y = pk2n(rl[2], rl[3]);
    size_t base = (size_t)n * KB + fbase;
    *reinterpret_cast<uint2*>(&g_Abig[base])       = hiv;
    *reinterpret_cast<uint2*>(&g_Abig[base + 256]) = hiv;
    *reinterpret_cast<uint2*>(&g_Abig[base + 512]) = lov;
}

// ---------------- host launcher ----------------
extern "C" void kernel_launch(void* const* d_in, const int* in_sizes, int n_in,
                              void* d_out, int out_size) {
    const float* x      = (const float*)d_in[0];
    const float* kpts   = (const float*)d_in[1];
    const float* pts3d  = (const float*)d_in[2];
    const float* pe_w1  = (const float*)d_in[3];
    const float* pe_b1  = (const float*)d_in[4];
    const float* pe_g1  = (const float*)d_in[5];
    const float* pe_bn1 = (const float*)d_in[6];
    const float* pe_w2  = (const float*)d_in[7];
    const float* pe_b2  = (const float*)d_in[8];
    const float* pe_g2  = (const float*)d_in[9];
    const float* pe_bn2 = (const float*)d_in[10];
    const float* lin_l_w = (const float*)d_in[11];
    const float* lin_l_b = (const float*)d_in[12];
    const float* lin_r_w = (const float*)d_in[13];
    const float* lin_r_b = (const float*)d_in[14];
    const float* lin_edge_w = (const float*)d_in[15];
    const float* att    = (const float*)d_in[16];
    const float* conv_b = (const float*)d_in[17];
    const float* norm_g = (const float*)d_in[18];
    const float* norm_b = (const float*)d_in[19];
    const float* res_w  = (const float*)d_in[20];
    const float* res_b  = (const float*)d_in[21];
    const float* proj_w = (const float*)d_in[22];
    const float* proj_b = (const float*)d_in[23];
    const int*   ei     = (const int*)d_in[24];
    float* out = (float*)d_out;

    static cudaStream_t s1 = nullptr;
    static cudaEvent_t evFork = nullptr, evJoin = nullptr;
    if (!s1) {
        cudaStreamCreateWithFlags(&s1, cudaStreamNonBlocking);
        cudaEventCreateWithFlags(&evFork, cudaEventDisableTiming);
        cudaEventCreateWithFlags(&evJoin, cudaEventDisableTiming);
        cudaFuncSetAttribute(k_mgemm, cudaFuncAttributeMaxDynamicSharedMemorySize, 4 * ABYTES);
        cudaFuncSetAttribute(k_mgemm1, cudaFuncAttributeMaxDynamicSharedMemorySize, 4 * ABYTES);
    }

    __nv_bfloat16* dA;  cudaGetSymbolAddress((void**)&dA,  g_Abig);
    __nv_bfloat16* dW;  cudaGetSymbolAddress((void**)&dW,  g_Wbig);
    __nv_bfloat16* dW2; cudaGetSymbolAddress((void**)&dW2, g_W2big);
    float* dB;    cudaGetSymbolAddress((void**)&dB,   g_B);
    float* dXL;   cudaGetSymbolAddress((void**)&dXL,  g_xl);
    float* dXRI;  cudaGetSymbolAddress((void**)&dXRI, g_xri);

    // slots 1-3: independent prep; slot 4: k_node (profiled)
    k_concat<<<768, 256>>>(lin_l_w, lin_r_w, res_w, lin_l_b, lin_r_b, res_b);
    k_splitW2<<<256, 256>>>(proj_w);
    k_init<<<(NN + 255) / 256, 256>>>();
    k_node<<<(NN + 7) / 8, 256>>>(x, kpts, pts3d, pe_w1, pe_b1, pe_g1, pe_bn1,
                                  pe_w2, pe_b2, pe_g2, pe_bn2);

    // fork: CSR histogram + scan run concurrently with gemm1
    cudaEventRecord(evFork, 0);
    cudaStreamWaitEvent(s1, evFork, 0);
    k_hist<<<(EE + 255) / 256, 256, 0, s1>>>(ei);
    k_scan1<<<196, 256, 0, s1>>>();
    k_scan2<<<1, 256, 0, s1>>>();
    k_scan3<<<196, 256, 0, s1>>>();
    cudaEventRecord(evJoin, s1);

    // gemm1 (merged): x_l -> g_xl, x_r|identity -> g_xri
    k_mgemm1<<<dim3(6, 391), 256, 4 * ABYTES>>>(dA, dW, dB, dXL, dXRI, NN);

    // join, then bucket (needs nuv from k_node + scan offsets)
    cudaStreamWaitEvent(0, evJoin, 0);
    k_bucket<<<(EE + 255) / 256, 256>>>(ei, out + NN * 256 + EE * 4);

    k_agg<<<12500, 256>>>(att, lin_edge_w, conv_b, norm_g, norm_b,
                          out + NN * 256);

    // gemm2: final projection
    k_mgemm<<<dim3(2, 391), 256, 4 * ABYTES>>>(dA, dW2, proj_b, out, NN, 256);
}

// round 13
// speedup vs baseline: 1.5277x; 1.5277x over previous
#include <cuda_runtime.h>
#include <cuda_bf16.h>
#include <math.h>
#include <stdint.h>

#define NN 50000
#define EE 800000
#define XD 192
#define MPAD 50048
#define KB 768          // split-K: [hi | hi | lo] x 256

// ---------------- scratch ----------------
static __device__ __nv_bfloat16 g_Abig[(size_t)MPAD * KB];   // A' splits
static __device__ __nv_bfloat16 g_Wbig[768 * KB];            // W' gemm1 (ll|lr|res)
static __device__ __nv_bfloat16 g_W2big[256 * KB];           // W' gemm2 (proj)
static __device__ float g_B[768];
static __device__ float g_w2t[64 * 32];                      // pe_w2 transposed: [j][out]
static __device__ float g_nuv[NN * 2];
static __device__ float g_xl[(size_t)NN * 256];              // x_l dense
static __device__ float g_xri[(size_t)NN * 512];             // x_r | identity
static __device__ float g_logits[EE * 4];                    // bucket-ordered
static __device__ float4 g_bgeo[EE];                         // (rx, ry, dist, src-bits)
static __device__ int   g_deg[NN];
static __device__ int   g_cur[NN];
static __device__ int   g_off[NN + 1];
static __device__ int   g_bkt[EE];
static __device__ int   g_bsum[256];

__device__ __forceinline__ float wsum(float v) {
#pragma unroll
    for (int o = 16; o > 0; o >>= 1) v += __shfl_xor_sync(0xffffffffu, v, o);
    return v;
}

__device__ __forceinline__ uint32_t pk2(float a, float b, float* ra, float* rb) {
    __nv_bfloat16 ha = __float2bfloat16(a), hb = __float2bfloat16(b);
    *ra = a - __bfloat162float(ha);
    *rb = b - __bfloat162float(hb);
    return (uint32_t)__bfloat16_as_ushort(ha) | ((uint32_t)__bfloat16_as_ushort(hb) << 16);
}
__device__ __forceinline__ uint32_t pk2n(float a, float b) {
    return (uint32_t)__bfloat16_as_ushort(__float2bfloat16(a)) |
           ((uint32_t)__bfloat16_as_ushort(__float2bfloat16(b)) << 16);
}

__device__ __forceinline__ uint32_t s2u(const void* p) {
    uint32_t a;
    asm("{ .reg .u64 t; cvta.to.shared.u64 t, %1; cvt.u32.u64 %0, t; }" : "=r"(a) : "l"(p));
    return a;
}

// ---------------- init ----------------
__global__ void k_init() {
    int t = blockIdx.x * blockDim.x + threadIdx.x;
    if (t < NN) { g_deg[t] = 0; g_cur[t] = 0; }
}

// ---------------- pos encoder + A' assembly (1 warp / node, coalesced w2t) ---------
__global__ void __launch_bounds__(256) k_node(const float* __restrict__ x,
                       const float* __restrict__ kpts,
                       const float* __restrict__ pts3d,
                       const float* __restrict__ w1, const float* __restrict__ b1,
                       const float* __restrict__ g1, const float* __restrict__ bn1,
                       const float* __restrict__ b2,
                       const float* __restrict__ g2, const float* __restrict__ bn2) {
    int gw = (blockIdx.x * blockDim.x + threadIdx.x) >> 5;
    int lane = threadIdx.x & 31;
    int w = threadIdx.x >> 5;
    if (gw >= NN) return;
    int n = gw;

    __shared__ float rowbuf[8][256];
    float* row = rowbuf[w];

    float nu = kpts[n * 2]     * (1.0f / 1216.0f);
    float nv = kpts[n * 2 + 1] * (1.0f / 352.0f);
    float dep = pts3d[n * 3 + 2];
    dep = fminf(fmaxf(dep, 0.1f), 100.0f);

    float h = nu * w1[lane * 3] + nv * w1[lane * 3 + 1] + dep * w1[lane * 3 + 2] + b1[lane];
    float mu = wsum(h) * (1.0f / 32.0f);
    float d = h - mu;
    float var = wsum(d * d) * (1.0f / 32.0f);
    float y = d * rsqrtf(var + 1e-5f) * g1[lane] + bn1[lane];
    y = y / (1.0f + __expf(-y));

    row[lane] = y;
    __syncwarp();

    // Linear(32,64) with transposed weights: coalesced loads, 1 line per LDG
    float o0 = b2[lane], o1 = b2[lane + 32];
#pragma unroll
    for (int j = 0; j < 32; j++) {
        float hv = row[j];
        o0 += hv * g_w2t[j * 64 + lane];
        o1 += hv * g_w2t[j * 64 + 32 + lane];
    }
    float mean = wsum(o0 + o1) * (1.0f / 64.0f);
    float d0 = o0 - mean, d1 = o1 - mean;
    float v2 = wsum(d0 * d0 + d1 * d1) * (1.0f / 64.0f);
    float r = rsqrtf(v2 + 1e-5f);
    float p0 = d0 * r * g2[lane] + bn2[lane];
    float p1 = d1 * r * g2[lane + 32] + bn2[lane + 32];
    __syncwarp();

    // assemble full 256-float row in smem
#pragma unroll
    for (int i = 0; i < 6; i++) row[lane + i * 32] = x[n * XD + lane + i * 32];
    row[192 + lane] = p0;
    row[224 + lane] = p1;
    __syncwarp();

    // each lane: 8 consecutive cols -> 3 x STG.128
    float v[8], rl[8];
#pragma unroll
    for (int k = 0; k < 8; k++) v[k] = row[lane * 8 + k];
    uint4 hiq, loq;
    hiq.x = pk2(v[0], v[1], &rl[0], &rl[1]);
    hiq.y = pk2(v[2], v[3], &rl[2], &rl[3]);
    hiq.z = pk2(v[4], v[5], &rl[4], &rl[5]);
    hiq.w = pk2(v[6], v[7], &rl[6], &rl[7]);
    loq.x = pk2n(rl[0], rl[1]);
    loq.y = pk2n(rl[2], rl[3]);
    loq.z = pk2n(rl[4], rl[5]);
    loq.w = pk2n(rl[6], rl[7]);

    size_t base = (size_t)n * KB + lane * 8;
    *reinterpret_cast<uint4*>(&g_Abig[base])       = hiq;
    *reinterpret_cast<uint4*>(&g_Abig[base + 256]) = hiq;
    *reinterpret_cast<uint4*>(&g_Abig[base + 512]) = loq;

    if (lane == 0) { g_nuv[2 * n] = nu; g_nuv[2 * n + 1] = nv; }
}

// ---------------- weight splits ----------------
__global__ void k_concat(const float* ll, const float* lr, const float* rw,
                         const float* lb, const float* rb, const float* resb) {
    int t = blockIdx.x * blockDim.x + threadIdx.x;
    if (t < 196608) {
        float v;
        if (t < 65536)       v = ll[t];
        else if (t < 131072) v = lr[t - 65536];
        else                 v = rw[t - 131072];
        int row = t >> 8, col = t & 255;
        __nv_bfloat16 h = __float2bfloat16(v);
        __nv_bfloat16 l = __float2bfloat16(v - __bfloat162float(h));
        g_Wbig[row * KB + col]       = h;
        g_Wbig[row * KB + 256 + col] = l;
        g_Wbig[row * KB + 512 + col] = h;
    }
    if (t < 256)       g_B[t] = lb[t];
    else if (t < 512)  g_B[t] = rb[t - 256];
    else if (t < 768)  g_B[t] = resb[t - 512];
}

// splitW2 + pe_w2 transpose folded into one launch (keeps k_node at slot 4)
__global__ void k_splitW2(const float* pw, const float* w2) {
    int t = blockIdx.x * blockDim.x + threadIdx.x;
    if (t < 65536) {
        float v = pw[t];
        int row = t >> 8, col = t & 255;
        __nv_bfloat16 h = __float2bfloat16(v);
        __nv_bfloat16 l = __float2bfloat16(v - __bfloat162float(h));
        g_W2big[row * KB + col]       = h;
        g_W2big[row * KB + 256 + col] = l;
        g_W2big[row * KB + 512 + col] = h;
    }
    if (t < 2048) {
        int out = t >> 5, j = t & 31;       // w2[out][j]
        g_w2t[j * 64 + out] = w2[t];
    }
}

// -------- mma.sync bf16 GEMM: C[M,*] = A'[M,768] * W'[Ncols,768]^T + bias --------
#define SSTRIDE 72
#define ABYTES  18432
__global__ void __launch_bounds__(256, 2) k_mgemm(const __nv_bfloat16* __restrict__ A,
                                                  const __nv_bfloat16* __restrict__ Bw,
                                                  const float* __restrict__ bias,
                                                  float* __restrict__ C, int M, int ldc) {
    extern __shared__ __align__(16) char smem[];
    const int tid = threadIdx.x, wid = tid >> 5, lane = tid & 31;
    const int mBase = blockIdx.y * 128;
    const int nBase = blockIdx.x * 128;
    const uint32_t sb = s2u(smem);
    const uint32_t sA[2] = {sb, sb + ABYTES};
    const uint32_t sB[2] = {sb + 2 * ABYTES, sb + 3 * ABYTES};

    const int wm = wid & 1;
    const int wn = wid >> 1;
    const int grp = lane >> 3;
    const int l8 = lane & 7;
    const int ldRow = tid >> 3;
    const int ldSeg = tid & 7;

    float c[4][4][4];
#pragma unroll
    for (int mt = 0; mt < 4; mt++)
#pragma unroll
        for (int nt = 0; nt < 4; nt++)
#pragma unroll
            for (int q = 0; q < 4; q++) c[mt][nt][q] = 0.0f;

    uint32_t aAddr[4];
#pragma unroll
    for (int mt = 0; mt < 4; mt++) {
        int row = wm * 64 + mt * 16 + (grp & 1) * 8 + l8;
        aAddr[mt] = (uint32_t)(row * (SSTRIDE * 2) + (grp >> 1) * 16);
    }
    uint32_t bAddr[2];
#pragma unroll
    for (int p = 0; p < 2; p++) {
        int nrow = wn * 32 + (2 * p + (grp >> 1)) * 8 + l8;
        bAddr[p] = (uint32_t)(nrow * (SSTRIDE * 2) + (grp & 1) * 16);
    }

    {
        const int b = 0, ch = 0;
#pragma unroll
        for (int i = 0; i < 4; i++) {
            int row = ldRow + i * 32;
            uint32_t sa = sA[b] + (uint32_t)(row * (SSTRIDE * 2) + ldSeg * 16);
            const __nv_bfloat16* ga = A + (size_t)(mBase + row) * KB + ch * 64 + ldSeg * 8;
            asm volatile("cp.async.cg.shared.global [%0], [%1], 16;" :: "r"(sa), "l"(ga));
            uint32_t sbb = sB[b] + (uint32_t)(row * (SSTRIDE * 2) + ldSeg * 16);
            const __nv_bfloat16* gb = Bw + (size_t)(nBase + row) * KB + ch * 64 + ldSeg * 8;
            asm volatile("cp.async.cg.shared.global [%0], [%1], 16;" :: "r"(sbb), "l"(gb));
        }
        asm volatile("cp.async.commit_group;" ::: "memory");
    }

    for (int ch = 0; ch < 12; ch++) {
        int b = ch & 1;
        if (ch + 1 < 12) {
            int nb = (ch + 1) & 1;
#pragma unroll
            for (int i = 0; i < 4; i++) {
                int row = ldRow + i * 32;
                uint32_t sa = sA[nb] + (uint32_t)(row * (SSTRIDE * 2) + ldSeg * 16);
                const __nv_bfloat16* ga = A + (size_t)(mBase + row) * KB + (ch + 1) * 64 + ldSeg * 8;
                asm volatile("cp.async.cg.shared.global [%0], [%1], 16;" :: "r"(sa), "l"(ga));
                uint32_t sbb = sB[nb] + (uint32_t)(row * (SSTRIDE * 2) + ldSeg * 16);
                const __nv_bfloat16* gb = Bw + (size_t)(nBase + row) * KB + (ch + 1) * 64 + ldSeg * 8;
                asm volatile("cp.async.cg.shared.global [%0], [%1], 16;" :: "r"(sbb), "l"(gb));
            }
            asm volatile("cp.async.commit_group;" ::: "memory");
            asm volatile("cp.async.wait_group 1;" ::: "memory");
        } else {
            asm volatile("cp.async.wait_group 0;" ::: "memory");
        }
        __syncthreads();

#pragma unroll
        for (int ks = 0; ks < 4; ks++) {
            uint32_t a[4][4], bb[4][2];
#pragma unroll
            for (int mt = 0; mt < 4; mt++) {
                uint32_t addr = sA[b] + aAddr[mt] + ks * 32;
                asm volatile("ldmatrix.sync.aligned.m8n8.x4.shared.b16 {%0,%1,%2,%3}, [%4];"
                             : "=r"(a[mt][0]), "=r"(a[mt][1]), "=r"(a[mt][2]), "=r"(a[mt][3])
                             : "r"(addr));
            }
#pragma unroll
            for (int p = 0; p < 2; p++) {
                uint32_t addr = sB[b] + bAddr[p] + ks * 32;
                asm volatile("ldmatrix.sync.aligned.m8n8.x4.shared.b16 {%0,%1,%2,%3}, [%4];"
                             : "=r"(bb[2 * p][0]), "=r"(bb[2 * p][1]),
                               "=r"(bb[2 * p + 1][0]), "=r"(bb[2 * p + 1][1])
                             : "r"(addr));
            }
#pragma unroll
            for (int mt = 0; mt < 4; mt++)
#pragma unroll
                for (int nt = 0; nt < 4; nt++) {
                    asm volatile(
                        "mma.sync.aligned.m16n8k16.row.col.f32.bf16.bf16.f32 "
                        "{%0,%1,%2,%3}, {%4,%5,%6,%7}, {%8,%9}, {%0,%1,%2,%3};"
                        : "+f"(c[mt][nt][0]), "+f"(c[mt][nt][1]),
                          "+f"(c[mt][nt][2]), "+f"(c[mt][nt][3])
                        : "r"(a[mt][0]), "r"(a[mt][1]), "r"(a[mt][2]), "r"(a[mt][3]),
                          "r"(bb[nt][0]), "r"(bb[nt][1]));
                }
        }
        __syncthreads();
    }

#pragma unroll
    for (int mt = 0; mt < 4; mt++) {
        int r0 = mBase + wm * 64 + mt * 16 + (lane >> 2);
        int r1 = r0 + 8;
#pragma unroll
        for (int nt = 0; nt < 4; nt++) {
            int col = nBase + wn * 32 + nt * 8 + (lane & 3) * 2;
            float b0 = bias[col], b1 = bias[col + 1];
            if (r0 < M) {
                float2 v = make_float2(c[mt][nt][0] + b0, c[mt][nt][1] + b1);
                *reinterpret_cast<float2*>(C + (size_t)r0 * ldc + col) = v;
            }
            if (r1 < M) {
                float2 v = make_float2(c[mt][nt][2] + b0, c[mt][nt][3] + b1);
                *reinterpret_cast<float2*>(C + (size_t)r1 * ldc + col) = v;
            }
        }
    }
}

// gemm1 wrapper: cols [0,256) -> g_xl (ldc 256), cols [256,768) -> g_xri (ldc 512)
__global__ void __launch_bounds__(256, 2) k_mgemm1(const __nv_bfloat16* __restrict__ A,
                                                   const __nv_bfloat16* __restrict__ Bw,
                                                   const float* __restrict__ bias,
                                                   float* __restrict__ Cxl,
                                                   float* __restrict__ Cxri, int M) {
    extern __shared__ __align__(16) char smem[];
    const int tid = threadIdx.x, wid = tid >> 5, lane = tid & 31;
    const int mBase = blockIdx.y * 128;
    const int bx = blockIdx.x;
    float* C; int ldc, nBase;
    if (bx < 2) { C = Cxl; ldc = 256; nBase = bx * 128; }
    else        { C = Cxri; ldc = 512; nBase = (bx - 2) * 128; }
    const int nBaseW = bx * 128;
    const uint32_t sb = s2u(smem);
    const uint32_t sA[2] = {sb, sb + ABYTES};
    const uint32_t sB[2] = {sb + 2 * ABYTES, sb + 3 * ABYTES};

    const int wm = wid & 1;
    const int wn = wid >> 1;
    const int grp = lane >> 3;
    const int l8 = lane & 7;
    const int ldRow = tid >> 3;
    const int ldSeg = tid & 7;

    float c[4][4][4];
#pragma unroll
    for (int mt = 0; mt < 4; mt++)
#pragma unroll
        for (int nt = 0; nt < 4; nt++)
#pragma unroll
            for (int q = 0; q < 4; q++) c[mt][nt][q] = 0.0f;

    uint32_t aAddr[4];
#pragma unroll
    for (int mt = 0; mt < 4; mt++) {
        int row = wm * 64 + mt * 16 + (grp & 1) * 8 + l8;
        aAddr[mt] = (uint32_t)(row * (SSTRIDE * 2) + (grp >> 1) * 16);
    }
    uint32_t bAddr[2];
#pragma unroll
    for (int p = 0; p < 2; p++) {
        int nrow = wn * 32 + (2 * p + (grp >> 1)) * 8 + l8;
        bAddr[p] = (uint32_t)(nrow * (SSTRIDE * 2) + (grp & 1) * 16);
    }

    {
        const int b = 0, ch = 0;
#pragma unroll
        for (int i = 0; i < 4; i++) {
            int row = ldRow + i * 32;
            uint32_t sa = sA[b] + (uint32_t)(row * (SSTRIDE * 2) + ldSeg * 16);
            const __nv_bfloat16* ga = A + (size_t)(mBase + row) * KB + ch * 64 + ldSeg * 8;
            asm volatile("cp.async.cg.shared.global [%0], [%1], 16;" :: "r"(sa), "l"(ga));
            uint32_t sbb = sB[b] + (uint32_t)(row * (SSTRIDE * 2) + ldSeg * 16);
            const __nv_bfloat16* gb = Bw + (size_t)(nBaseW + row) * KB + ch * 64 + ldSeg * 8;
            asm volatile("cp.async.cg.shared.global [%0], [%1], 16;" :: "r"(sbb), "l"(gb));
        }
        asm volatile("cp.async.commit_group;" ::: "memory");
    }

    for (int ch = 0; ch < 12; ch++) {
        int b = ch & 1;
        if (ch + 1 < 12) {
            int nb = (ch + 1) & 1;
#pragma unroll
            for (int i = 0; i < 4; i++) {
                int row = ldRow + i * 32;
                uint32_t sa = sA[nb] + (uint32_t)(row * (SSTRIDE * 2) + ldSeg * 16);
                const __nv_bfloat16* ga = A + (size_t)(mBase + row) * KB + (ch + 1) * 64 + ldSeg * 8;
                asm volatile("cp.async.cg.shared.global [%0], [%1], 16;" :: "r"(sa), "l"(ga));
                uint32_t sbb = sB[nb] + (uint32_t)(row * (SSTRIDE * 2) + ldSeg * 16);
                const __nv_bfloat16* gb = Bw + (size_t)(nBaseW + row) * KB + (ch + 1) * 64 + ldSeg * 8;
                asm volatile("cp.async.cg.shared.global [%0], [%1], 16;" :: "r"(sbb), "l"(gb));
            }
            asm volatile("cp.async.commit_group;" ::: "memory");
            asm volatile("cp.async.wait_group 1;" ::: "memory");
        } else {
            asm volatile("cp.async.wait_group 0;" ::: "memory");
        }
        __syncthreads();

#pragma unroll
        for (int ks = 0; ks < 4; ks++) {
            uint32_t a[4][4], bb[4][2];
#pragma unroll
            for (int mt = 0; mt < 4; mt++) {
                uint32_t addr = sA[b] + aAddr[mt] + ks * 32;
                asm volatile("ldmatrix.sync.aligned.m8n8.x4.shared.b16 {%0,%1,%2,%3}, [%4];"
                             : "=r"(a[mt][0]), "=r"(a[mt][1]), "=r"(a[mt][2]), "=r"(a[mt][3])
                             : "r"(addr));
            }
#pragma unroll
            for (int p = 0; p < 2; p++) {
                uint32_t addr = sB[b] + bAddr[p] + ks * 32;
                asm volatile("ldmatrix.sync.aligned.m8n8.x4.shared.b16 {%0,%1,%2,%3}, [%4];"
                             : "=r"(bb[2 * p][0]), "=r"(bb[2 * p][1]),
                               "=r"(bb[2 * p + 1][0]), "=r"(bb[2 * p + 1][1])
                             : "r"(addr));
            }
#pragma unroll
            for (int mt = 0; mt < 4; mt++)
#pragma unroll
                for (int nt = 0; nt < 4; nt++) {
                    asm volatile(
                        "mma.sync.aligned.m16n8k16.row.col.f32.bf16.bf16.f32 "
                        "{%0,%1,%2,%3}, {%4,%5,%6,%7}, {%8,%9}, {%0,%1,%2,%3};"
                        : "+f"(c[mt][nt][0]), "+f"(c[mt][nt][1]),
                          "+f"(c[mt][nt][2]), "+f"(c[mt][nt][3])
                        : "r"(a[mt][0]), "r"(a[mt][1]), "r"(a[mt][2]), "r"(a[mt][3]),
                          "r"(bb[nt][0]), "r"(bb[nt][1]));
                }
        }
        __syncthreads();
    }

#pragma unroll
    for (int mt = 0; mt < 4; mt++) {
        int r0 = mBase + wm * 64 + mt * 16 + (lane >> 2);
        int r1 = r0 + 8;
#pragma unroll
        for (int nt = 0; nt < 4; nt++) {
            int colW = nBaseW + wn * 32 + nt * 8 + (lane & 3) * 2;
            int col = nBase + wn * 32 + nt * 8 + (lane & 3) * 2;
            float b0 = bias[colW], b1 = bias[colW + 1];
            if (r0 < M) {
                float2 v = make_float2(c[mt][nt][0] + b0, c[mt][nt][1] + b1);
                *reinterpret_cast<float2*>(C + (size_t)r0 * ldc + col) = v;
            }
            if (r1 < M) {
                float2 v = make_float2(c[mt][nt][2] + b0, c[mt][nt][3] + b1);
                *reinterpret_cast<float2*>(C + (size_t)r1 * ldc + col) = v;
            }
        }
    }
}

// ---------------- CSR build ----------------
__global__ void k_hist(const int* __restrict__ ei) {
    int t = blockIdx.x * blockDim.x + threadIdx.x;
    if (t < EE) atomicAdd(&g_deg[ei[EE + t]], 1);
}

__global__ void k_scan1() {
    __shared__ int sh[256];
    int b = blockIdx.x, tid = threadIdx.x;
    int i = b * 256 + tid;
    int v = (i < NN) ? g_deg[i] : 0;
    sh[tid] = v;
    __syncthreads();
    for (int o = 1; o < 256; o <<= 1) {
        int t = (tid >= o) ? sh[tid - o] : 0;
        __syncthreads();
        sh[tid] += t;
        __syncthreads();
    }
    if (i < NN) g_off[i] = sh[tid] - v;
    if (tid == 255) g_bsum[b] = sh[255];
}

__global__ void k_scan2() {
    __shared__ int sh[256];
    int tid = threadIdx.x;
    int v = (tid < 196) ? g_bsum[tid] : 0;
    sh[tid] = v;
    __syncthreads();
    for (int o = 1; o < 256; o <<= 1) {
        int t = (tid >= o) ? sh[tid - o] : 0;
        __syncthreads();
        sh[tid] += t;
        __syncthreads();
    }
    g_bsum[tid] = sh[tid] - v;
}

__global__ void k_scan3() {
    int i = blockIdx.x * 256 + threadIdx.x;
    if (i < NN) g_off[i] += g_bsum[blockIdx.x];
    if (i == 0) g_off[NN] = EE;
}

// bucket fill + geometry precompute + edge_attr output
__global__ void k_bucket(const int* __restrict__ ei, float* __restrict__ outE) {
    int t = blockIdx.x * blockDim.x + threadIdx.x;
    if (t < EE) {
        int s = ei[t];
        int d = ei[EE + t];
        int p = atomicAdd(&g_cur[d], 1);
        int pos = g_off[d] + p;
        g_bkt[pos] = t;
        const float2* nuv2 = (const float2*)g_nuv;
        float2 nd = nuv2[d], ns = nuv2[s];
        float rx = nd.x - ns.x;
        float ry = nd.y - ns.y;
        float dd = sqrtf(rx * rx + ry * ry);
        g_bgeo[pos] = make_float4(rx, ry, dd, __int_as_float(s));
        outE[(size_t)t * 3]     = rx;
        outE[(size_t)t * 3 + 1] = ry;
        outE[(size_t)t * 3 + 2] = dd;
    }
}

// ------- per-node attention: 2 warps/node, dual-state softmax, alpha, LN, SiLU -------
__global__ void __launch_bounds__(256) k_agg(const float* __restrict__ att,
                      const float* __restrict__ We, const float* __restrict__ cb,
                      const float* __restrict__ ng, const float* __restrict__ nb,
                      float* __restrict__ outA) {
    int gw = (blockIdx.x * blockDim.x + threadIdx.x) >> 5;
    int lane = threadIdx.x & 31;
    int wib = (threadIdx.x >> 5);
    int n = gw >> 1;
    int w = gw & 1;

    int fbase = w * 128 + lane * 4;
    float attv[4], we0[4], we1[4], we2[4], xr[4], accA[4], accB[4];
#pragma unroll
    for (int k = 0; k < 4; k++) {
        int j = fbase + k;
        attv[k] = att[j];
        we0[k] = We[j * 3]; we1[k] = We[j * 3 + 1]; we2[k] = We[j * 3 + 2];
        accA[k] = 0.0f; accB[k] = 0.0f;
    }
    {
        float4 a = ((const float4*)&g_xri[(size_t)n * 512 + w * 128])[lane];
        xr[0] = a.x; xr[1] = a.y; xr[2] = a.z; xr[3] = a.w;
    }
    float mA = -3.0e38f, sA = 0.0f, mB = -3.0e38f, sB = 0.0f;
    int beg = g_off[n], end = g_off[n + 1];
    int hsel = w * 2 + (lane >> 4);

    int i = beg;
    float4 gA = make_float4(0.f,0.f,0.f,0.f), gB = gA, xA = gA, xB = gA;
    if (i + 1 < end) {
        gA = g_bgeo[i]; gB = g_bgeo[i + 1];
        xA = ((const float4*)&g_xl[(size_t)__float_as_int(gA.w) * 256 + w * 128])[lane];
        xB = ((const float4*)&g_xl[(size_t)__float_as_int(gB.w) * 256 + w * 128])[lane];
    }
    while (i + 1 < end) {
        float4 cgA = gA, cgB = gB;
        float xlA[4] = {xA.x, xA.y, xA.z, xA.w};
        float xlB[4] = {xB.x, xB.y, xB.z, xB.w};
        int ni = i + 2;
        if (ni + 1 < end) {
            gA = g_bgeo[ni]; gB = g_bgeo[ni + 1];
            xA = ((const float4*)&g_xl[(size_t)__float_as_int(gA.w) * 256 + w * 128])[lane];
            xB = ((const float4*)&g_xl[(size_t)__float_as_int(gB.w) * 256 + w * 128])[lane];
        }
        float ppA = 0.0f, ppB = 0.0f;
#pragma unroll
        for (int k = 0; k < 4; k++) {
            float zA = xlA[k] + xr[k] + (cgA.x * we0[k] + cgA.y * we1[k] + cgA.z * we2[k]);
            float zB = xlB[k] + xr[k] + (cgB.x * we0[k] + cgB.y * we1[k] + cgB.z * we2[k]);
            zA = (zA > 0.0f) ? zA : 0.2f * zA;
            zB = (zB > 0.0f) ? zB : 0.2f * zB;
            ppA += zA * attv[k];
            ppB += zB * attv[k];
        }
#pragma unroll
        for (int o = 1; o < 16; o <<= 1) {
            ppA += __shfl_xor_sync(0xffffffffu, ppA, o);
            ppB += __shfl_xor_sync(0xffffffffu, ppB, o);
        }
        if ((lane & 15) == 0) {
            g_logits[i * 4 + hsel]       = ppA;
            g_logits[(i + 1) * 4 + hsel] = ppB;
        }
        {
            float mn = fmaxf(mA, ppA);
            float sc = __expf(mA - mn);
            float p = __expf(ppA - mn);
            sA = sA * sc + p;
            mA = mn;
#pragma unroll
            for (int k = 0; k < 4; k++) accA[k] = accA[k] * sc + p * xlA[k];
        }
        {
            float mn = fmaxf(mB, ppB);
            float sc = __expf(mB - mn);
            float p = __expf(ppB - mn);
            sB = sB * sc + p;
            mB = mn;
#pragma unroll
            for (int k = 0; k < 4; k++) accB[k] = accB[k] * sc + p * xlB[k];
        }
        i = ni;
    }
    if (i < end) {
        float4 g = g_bgeo[i];
        float4 xa = ((const float4*)&g_xl[(size_t)__float_as_int(g.w) * 256 + w * 128])[lane];
        float xl[4] = {xa.x, xa.y, xa.z, xa.w};
        float pp = 0.0f;
#pragma unroll
        for (int k = 0; k < 4; k++) {
            float z = xl[k] + xr[k] + (g.x * we0[k] + g.y * we1[k] + g.z * we2[k]);
            z = (z > 0.0f) ? z : 0.2f * z;
            pp += z * attv[k];
        }
#pragma unroll
        for (int o = 1; o < 16; o <<= 1) pp += __shfl_xor_sync(0xffffffffu, pp, o);
        if ((lane & 15) == 0) g_logits[i * 4 + hsel] = pp;
        float mn = fmaxf(mA, pp);
        float sc = __expf(mA - mn);
        float p = __expf(pp - mn);
        sA = sA * sc + p;
        mA = mn;
#pragma unroll
        for (int k = 0; k < 4; k++) accA[k] = accA[k] * sc + p * xl[k];
    }

    float m = fmaxf(mA, mB);
    float eA = __expf(mA - m), eB = __expf(mB - m);
    float s = sA * eA + sB * eB;
    float acc[4];
#pragma unroll
    for (int k = 0; k < 4; k++) acc[k] = accA[k] * eA + accB[k] * eB;

    __threadfence_block();
    __syncwarp();
    {
        float mh0 = __shfl_sync(0xffffffffu, m, 0);
        float mh1 = __shfl_sync(0xffffffffu, m, 16);
        float ih0 = 1.0f / (__shfl_sync(0xffffffffu, s, 0)  + 1e-16f);
        float ih1 = 1.0f / (__shfl_sync(0xffffffffu, s, 16) + 1e-16f);
        int deg = end - beg;
        for (int j = lane; j < deg; j += 32) {
            int pos = beg + j;
            float2 lg = *(const float2*)&g_logits[(size_t)pos * 4 + w * 2];
            int e = g_bkt[pos];
            float2 av;
            av.x = __expf(lg.x - mh0) * ih0;
            av.y = __expf(lg.y - mh1) * ih1;
            *(float2*)&outA[(size_t)e * 4 + w * 2] = av;
        }
    }

    float inv = (end > beg) ? (1.0f / s) : 0.0f;
    float o[4];
#pragma unroll
    for (int k = 0; k < 4; k++) o[k] = acc[k] * inv + cb[fbase + k];

    __shared__ float sSum[8], sVar[8];
    float ps = o[0] + o[1] + o[2] + o[3];
    ps = wsum(ps);
    if (lane == 0) sSum[wib] = ps;
    __syncthreads();
    float mean = (sSum[wib ^ 1] + ps) * (1.0f / 256.0f);
    float pv = 0.0f;
#pragma unroll
    for (int k = 0; k < 4; k++) { float d = o[k] - mean; pv += d * d; }
    pv = wsum(pv);
    if (lane == 0) sVar[wib] = pv;
    __syncthreads();
    float var = (sVar[wib ^ 1] + pv) * (1.0f / 256.0f);
    float r = rsqrtf(var + 1e-5f);

    float4 iv = ((const float4*)&g_xri[(size_t)n * 512 + 256 + w * 128])[lane];
    float idv[4] = {iv.x, iv.y, iv.z, iv.w};
    float y[4];
#pragma unroll
    for (int k = 0; k < 4; k++) {
        int j = fbase + k;
        float t = (o[k] - mean) * r * ng[j] + nb[j] + idv[k];
        y[k] = t / (1.0f + __expf(-t));
    }
    float rl[4];
    uint2 hiv, lov;
    hiv.x = pk2(y[0], y[1], &rl[0], &rl[1]);
    hiv.y = pk2(y[2], y[3], &rl[2], &rl[3]);
    lov.x = pk2n(rl[0], rl[1]);
    lov.y = pk2n(rl[2], rl[3]);
    size_t base = (size_t)n * KB + fbase;
    *reinterpret_cast<uint2*>(&g_Abig[base])       = hiv;
    *reinterpret_cast<uint2*>(&g_Abig[base + 256]) = hiv;
    *reinterpret_cast<uint2*>(&g_Abig[base + 512]) = lov;
}

// ---------------- host launcher ----------------
extern "C" void kernel_launch(void* const* d_in, const int* in_sizes, int n_in,
                              void* d_out, int out_size) {
    const float* x      = (const float*)d_in[0];
    const float* kpts   = (const float*)d_in[1];
    const float* pts3d  = (const float*)d_in[2];
    const float* pe_w1  = (const float*)d_in[3];
    const float* pe_b1  = (const float*)d_in[4];
    const float* pe_g1  = (const float*)d_in[5];
    const float* pe_bn1 = (const float*)d_in[6];
    const float* pe_w2  = (const float*)d_in[7];
    const float* pe_b2  = (const float*)d_in[8];
    const float* pe_g2  = (const float*)d_in[9];
    const float* pe_bn2 = (const float*)d_in[10];
    const float* lin_l_w = (const float*)d_in[11];
    const float* lin_l_b = (const float*)d_in[12];
    const float* lin_r_w = (const float*)d_in[13];
    const float* lin_r_b = (const float*)d_in[14];
    const float* lin_edge_w = (const float*)d_in[15];
    const float* att    = (const float*)d_in[16];
    const float* conv_b = (const float*)d_in[17];
    const float* norm_g = (const float*)d_in[18];
    const float* norm_b = (const float*)d_in[19];
    const float* res_w  = (const float*)d_in[20];
    const float* res_b  = (const float*)d_in[21];
    const float* proj_w = (const float*)d_in[22];
    const float* proj_b = (const float*)d_in[23];
    const int*   ei     = (const int*)d_in[24];
    float* out = (float*)d_out;

    static cudaStream_t s1 = nullptr;
    static cudaEvent_t evFork = nullptr, evJoin = nullptr;
    if (!s1) {
        cudaStreamCreateWithFlags(&s1, cudaStreamNonBlocking);
        cudaEventCreateWithFlags(&evFork, cudaEventDisableTiming);
        cudaEventCreateWithFlags(&evJoin, cudaEventDisableTiming);
        cudaFuncSetAttribute(k_mgemm, cudaFuncAttributeMaxDynamicSharedMemorySize, 4 * ABYTES);
        cudaFuncSetAttribute(k_mgemm1, cudaFuncAttributeMaxDynamicSharedMemorySize, 4 * ABYTES);
    }

    __nv_bfloat16* dA;  cudaGetSymbolAddress((void**)&dA,  g_Abig);
    __nv_bfloat16* dW;  cudaGetSymbolAddress((void**)&dW,  g_Wbig);
    __nv_bfloat16* dW2; cudaGetSymbolAddress((void**)&dW2, g_W2big);
    float* dB;    cudaGetSymbolAddress((void**)&dB,   g_B);
    float* dXL;   cudaGetSymbolAddress((void**)&dXL,  g_xl);
    float* dXRI;  cudaGetSymbolAddress((void**)&dXRI, g_xri);

    // slots 1-3: independent prep; slot 4: k_node (profiled)
    k_concat<<<768, 256>>>(lin_l_w, lin_r_w, res_w, lin_l_b, lin_r_b, res_b);
    k_splitW2<<<256, 256>>>(proj_w, pe_w2);
    k_init<<<(NN + 255) / 256, 256>>>();
    k_node<<<(NN + 7) / 8, 256>>>(x, kpts, pts3d, pe_w1, pe_b1, pe_g1, pe_bn1,
                                  pe_b2, pe_g2, pe_bn2);

    // fork: CSR histogram + scan run concurrently with gemm1
    cudaEventRecord(evFork, 0);
    cudaStreamWaitEvent(s1, evFork, 0);
    k_hist<<<(EE + 255) / 256, 256, 0, s1>>>(ei);
    k_scan1<<<196, 256, 0, s1>>>();
    k_scan2<<<1, 256, 0, s1>>>();
    k_scan3<<<196, 256, 0, s1>>>();
    cudaEventRecord(evJoin, s1);

    // gemm1 (merged): x_l -> g_xl, x_r|identity -> g_xri
    k_mgemm1<<<dim3(6, 391), 256, 4 * ABYTES>>>(dA, dW, dB, dXL, dXRI, NN);

    // join, then bucket (needs nuv from k_node + scan offsets)
    cudaStreamWaitEvent(0, evJoin, 0);
    k_bucket<<<(EE + 255) / 256, 256>>>(ei, out + NN * 256 + EE * 4);

    k_agg<<<12500, 256>>>(att, lin_edge_w, conv_b, norm_g, norm_b,
                          out + NN * 256);

    // gemm2: final projection
    k_mgemm<<<dim3(2, 391), 256, 4 * ABYTES>>>(dA, dW2, proj_b, out, NN, 256);
}

// round 14
// speedup vs baseline: 1.5319x; 1.0027x over previous
#include <cuda_runtime.h>
#include <cuda_bf16.h>
#include <math.h>
#include <stdint.h>

#define NN 50000
#define EE 800000
#define XD 192
#define MPAD 50048
#define KB 768          // split-K: [hi | hi | lo] x 256

// ---------------- scratch ----------------
static __device__ __nv_bfloat16 g_Abig[(size_t)MPAD * KB];   // A' splits
static __device__ __nv_bfloat16 g_Wbig[768 * KB];            // W' gemm1 (ll|lr|res)
static __device__ __nv_bfloat16 g_W2big[256 * KB];           // W' gemm2 (proj)
static __device__ float g_B[768];
static __device__ float g_w2t[64 * 32];                      // pe_w2 transposed: [j][out]
static __device__ float g_nuv[NN * 2];
static __device__ float g_xl[(size_t)NN * 256];              // x_l dense
static __device__ float g_xri[(size_t)NN * 512];             // x_r | identity
static __device__ float g_logits[EE * 4];                    // bucket-ordered
static __device__ float4 g_bgeo[EE];                         // (rx, ry, dist, src-bits)
static __device__ int   g_deg[NN];
static __device__ int   g_cur[NN];
static __device__ int   g_off[NN + 1];
static __device__ int   g_bkt[EE];
static __device__ int   g_bsum[256];

__device__ __forceinline__ float wsum(float v) {
#pragma unroll
    for (int o = 16; o > 0; o >>= 1) v += __shfl_xor_sync(0xffffffffu, v, o);
    return v;
}

__device__ __forceinline__ uint32_t pk2(float a, float b, float* ra, float* rb) {
    __nv_bfloat16 ha = __float2bfloat16(a), hb = __float2bfloat16(b);
    *ra = a - __bfloat162float(ha);
    *rb = b - __bfloat162float(hb);
    return (uint32_t)__bfloat16_as_ushort(ha) | ((uint32_t)__bfloat16_as_ushort(hb) << 16);
}
__device__ __forceinline__ uint32_t pk2n(float a, float b) {
    return (uint32_t)__bfloat16_as_ushort(__float2bfloat16(a)) |
           ((uint32_t)__bfloat16_as_ushort(__float2bfloat16(b)) << 16);
}

__device__ __forceinline__ uint32_t s2u(const void* p) {
    uint32_t a;
    asm("{ .reg .u64 t; cvta.to.shared.u64 t, %1; cvt.u32.u64 %0, t; }" : "=r"(a) : "l"(p));
    return a;
}

// ---------------- init ----------------
__global__ void k_init() {
    int t = blockIdx.x * blockDim.x + threadIdx.x;
    if (t < NN) { g_deg[t] = 0; g_cur[t] = 0; }
}

// ---------------- pos encoder + A' assembly (1 warp / node, coalesced w2t) ---------
__global__ void __launch_bounds__(256) k_node(const float* __restrict__ x,
                       const float* __restrict__ kpts,
                       const float* __restrict__ pts3d,
                       const float* __restrict__ w1, const float* __restrict__ b1,
                       const float* __restrict__ g1, const float* __restrict__ bn1,
                       const float* __restrict__ b2,
                       const float* __restrict__ g2, const float* __restrict__ bn2) {
    int gw = (blockIdx.x * blockDim.x + threadIdx.x) >> 5;
    int lane = threadIdx.x & 31;
    int w = threadIdx.x >> 5;
    if (gw >= NN) return;
    int n = gw;

    __shared__ float rowbuf[8][256];
    float* row = rowbuf[w];

    float nu = kpts[n * 2]     * (1.0f / 1216.0f);
    float nv = kpts[n * 2 + 1] * (1.0f / 352.0f);
    float dep = pts3d[n * 3 + 2];
    dep = fminf(fmaxf(dep, 0.1f), 100.0f);

    float h = nu * w1[lane * 3] + nv * w1[lane * 3 + 1] + dep * w1[lane * 3 + 2] + b1[lane];
    float mu = wsum(h) * (1.0f / 32.0f);
    float d = h - mu;
    float var = wsum(d * d) * (1.0f / 32.0f);
    float y = d * rsqrtf(var + 1e-5f) * g1[lane] + bn1[lane];
    y = y / (1.0f + __expf(-y));

    row[lane] = y;
    __syncwarp();

    float o0 = b2[lane], o1 = b2[lane + 32];
#pragma unroll
    for (int j = 0; j < 32; j++) {
        float hv = row[j];
        o0 += hv * g_w2t[j * 64 + lane];
        o1 += hv * g_w2t[j * 64 + 32 + lane];
    }
    float mean = wsum(o0 + o1) * (1.0f / 64.0f);
    float d0 = o0 - mean, d1 = o1 - mean;
    float v2 = wsum(d0 * d0 + d1 * d1) * (1.0f / 64.0f);
    float r = rsqrtf(v2 + 1e-5f);
    float p0 = d0 * r * g2[lane] + bn2[lane];
    float p1 = d1 * r * g2[lane + 32] + bn2[lane + 32];
    __syncwarp();

#pragma unroll
    for (int i = 0; i < 6; i++) row[lane + i * 32] = x[n * XD + lane + i * 32];
    row[192 + lane] = p0;
    row[224 + lane] = p1;
    __syncwarp();

    float v[8], rl[8];
#pragma unroll
    for (int k = 0; k < 8; k++) v[k] = row[lane * 8 + k];
    uint4 hiq, loq;
    hiq.x = pk2(v[0], v[1], &rl[0], &rl[1]);
    hiq.y = pk2(v[2], v[3], &rl[2], &rl[3]);
    hiq.z = pk2(v[4], v[5], &rl[4], &rl[5]);
    hiq.w = pk2(v[6], v[7], &rl[6], &rl[7]);
    loq.x = pk2n(rl[0], rl[1]);
    loq.y = pk2n(rl[2], rl[3]);
    loq.z = pk2n(rl[4], rl[5]);
    loq.w = pk2n(rl[6], rl[7]);

    size_t base = (size_t)n * KB + lane * 8;
    *reinterpret_cast<uint4*>(&g_Abig[base])       = hiq;
    *reinterpret_cast<uint4*>(&g_Abig[base + 256]) = hiq;
    *reinterpret_cast<uint4*>(&g_Abig[base + 512]) = loq;

    if (lane == 0) { g_nuv[2 * n] = nu; g_nuv[2 * n + 1] = nv; }
}

// ---------------- weight splits ----------------
__global__ void k_concat(const float* ll, const float* lr, const float* rw,
                         const float* lb, const float* rb, const float* resb) {
    int t = blockIdx.x * blockDim.x + threadIdx.x;
    if (t < 196608) {
        float v;
        if (t < 65536)       v = ll[t];
        else if (t < 131072) v = lr[t - 65536];
        else                 v = rw[t - 131072];
        int row = t >> 8, col = t & 255;
        __nv_bfloat16 h = __float2bfloat16(v);
        __nv_bfloat16 l = __float2bfloat16(v - __bfloat162float(h));
        g_Wbig[row * KB + col]       = h;
        g_Wbig[row * KB + 256 + col] = l;
        g_Wbig[row * KB + 512 + col] = h;
    }
    if (t < 256)       g_B[t] = lb[t];
    else if (t < 512)  g_B[t] = rb[t - 256];
    else if (t < 768)  g_B[t] = resb[t - 512];
}

__global__ void k_splitW2(const float* pw, const float* w2) {
    int t = blockIdx.x * blockDim.x + threadIdx.x;
    if (t < 65536) {
        float v = pw[t];
        int row = t >> 8, col = t & 255;
        __nv_bfloat16 h = __float2bfloat16(v);
        __nv_bfloat16 l = __float2bfloat16(v - __bfloat162float(h));
        g_W2big[row * KB + col]       = h;
        g_W2big[row * KB + 256 + col] = l;
        g_W2big[row * KB + 512 + col] = h;
    }
    if (t < 2048) {
        int out = t >> 5, j = t & 31;
        g_w2t[j * 64 + out] = w2[t];
    }
}

// -------- mma.sync bf16 GEMM: C[M,*] = A'[M,768] * W'[Ncols,768]^T + bias --------
#define SSTRIDE 72
#define ABYTES  18432
__global__ void __launch_bounds__(256, 2) k_mgemm(const __nv_bfloat16* __restrict__ A,
                                                  const __nv_bfloat16* __restrict__ Bw,
                                                  const float* __restrict__ bias,
                                                  float* __restrict__ C, int M, int ldc) {
    extern __shared__ __align__(16) char smem[];
    const int tid = threadIdx.x, wid = tid >> 5, lane = tid & 31;
    const int mBase = blockIdx.y * 128;
    const int nBase = blockIdx.x * 128;
    const uint32_t sb = s2u(smem);
    const uint32_t sA[2] = {sb, sb + ABYTES};
    const uint32_t sB[2] = {sb + 2 * ABYTES, sb + 3 * ABYTES};

    const int wm = wid & 1;
    const int wn = wid >> 1;
    const int grp = lane >> 3;
    const int l8 = lane & 7;
    const int ldRow = tid >> 3;
    const int ldSeg = tid & 7;

    float c[4][4][4];
#pragma unroll
    for (int mt = 0; mt < 4; mt++)
#pragma unroll
        for (int nt = 0; nt < 4; nt++)
#pragma unroll
            for (int q = 0; q < 4; q++) c[mt][nt][q] = 0.0f;

    uint32_t aAddr[4];
#pragma unroll
    for (int mt = 0; mt < 4; mt++) {
        int row = wm * 64 + mt * 16 + (grp & 1) * 8 + l8;
        aAddr[mt] = (uint32_t)(row * (SSTRIDE * 2) + (grp >> 1) * 16);
    }
    uint32_t bAddr[2];
#pragma unroll
    for (int p = 0; p < 2; p++) {
        int nrow = wn * 32 + (2 * p + (grp >> 1)) * 8 + l8;
        bAddr[p] = (uint32_t)(nrow * (SSTRIDE * 2) + (grp & 1) * 16);
    }

    {
        const int b = 0, ch = 0;
#pragma unroll
        for (int i = 0; i < 4; i++) {
            int row = ldRow + i * 32;
            uint32_t sa = sA[b] + (uint32_t)(row * (SSTRIDE * 2) + ldSeg * 16);
            const __nv_bfloat16* ga = A + (size_t)(mBase + row) * KB + ch * 64 + ldSeg * 8;
            asm volatile("cp.async.cg.shared.global [%0], [%1], 16;" :: "r"(sa), "l"(ga));
            uint32_t sbb = sB[b] + (uint32_t)(row * (SSTRIDE * 2) + ldSeg * 16);
            const __nv_bfloat16* gb = Bw + (size_t)(nBase + row) * KB + ch * 64 + ldSeg * 8;
            asm volatile("cp.async.cg.shared.global [%0], [%1], 16;" :: "r"(sbb), "l"(gb));
        }
        asm volatile("cp.async.commit_group;" ::: "memory");
    }

    for (int ch = 0; ch < 12; ch++) {
        int b = ch & 1;
        if (ch + 1 < 12) {
            int nb = (ch + 1) & 1;
#pragma unroll
            for (int i = 0; i < 4; i++) {
                int row = ldRow + i * 32;
                uint32_t sa = sA[nb] + (uint32_t)(row * (SSTRIDE * 2) + ldSeg * 16);
                const __nv_bfloat16* ga = A + (size_t)(mBase + row) * KB + (ch + 1) * 64 + ldSeg * 8;
                asm volatile("cp.async.cg.shared.global [%0], [%1], 16;" :: "r"(sa), "l"(ga));
                uint32_t sbb = sB[nb] + (uint32_t)(row * (SSTRIDE * 2) + ldSeg * 16);
                const __nv_bfloat16* gb = Bw + (size_t)(nBase + row) * KB + (ch + 1) * 64 + ldSeg * 8;
                asm volatile("cp.async.cg.shared.global [%0], [%1], 16;" :: "r"(sbb), "l"(gb));
            }
            asm volatile("cp.async.commit_group;" ::: "memory");
            asm volatile("cp.async.wait_group 1;" ::: "memory");
        } else {
            asm volatile("cp.async.wait_group 0;" ::: "memory");
        }
        __syncthreads();

#pragma unroll
        for (int ks = 0; ks < 4; ks++) {
            uint32_t a[4][4], bb[4][2];
#pragma unroll
            for (int mt = 0; mt < 4; mt++) {
                uint32_t addr = sA[b] + aAddr[mt] + ks * 32;
                asm volatile("ldmatrix.sync.aligned.m8n8.x4.shared.b16 {%0,%1,%2,%3}, [%4];"
                             : "=r"(a[mt][0]), "=r"(a[mt][1]), "=r"(a[mt][2]), "=r"(a[mt][3])
                             : "r"(addr));
            }
#pragma unroll
            for (int p = 0; p < 2; p++) {
                uint32_t addr = sB[b] + bAddr[p] + ks * 32;
                asm volatile("ldmatrix.sync.aligned.m8n8.x4.shared.b16 {%0,%1,%2,%3}, [%4];"
                             : "=r"(bb[2 * p][0]), "=r"(bb[2 * p][1]),
                               "=r"(bb[2 * p + 1][0]), "=r"(bb[2 * p + 1][1])
                             : "r"(addr));
            }
#pragma unroll
            for (int mt = 0; mt < 4; mt++)
#pragma unroll
                for (int nt = 0; nt < 4; nt++) {
                    asm volatile(
                        "mma.sync.aligned.m16n8k16.row.col.f32.bf16.bf16.f32 "
                        "{%0,%1,%2,%3}, {%4,%5,%6,%7}, {%8,%9}, {%0,%1,%2,%3};"
                        : "+f"(c[mt][nt][0]), "+f"(c[mt][nt][1]),
                          "+f"(c[mt][nt][2]), "+f"(c[mt][nt][3])
                        : "r"(a[mt][0]), "r"(a[mt][1]), "r"(a[mt][2]), "r"(a[mt][3]),
                          "r"(bb[nt][0]), "r"(bb[nt][1]));
                }
        }
        __syncthreads();
    }

#pragma unroll
    for (int mt = 0; mt < 4; mt++) {
        int r0 = mBase + wm * 64 + mt * 16 + (lane >> 2);
        int r1 = r0 + 8;
#pragma unroll
        for (int nt = 0; nt < 4; nt++) {
            int col = nBase + wn * 32 + nt * 8 + (lane & 3) * 2;
            float b0 = bias[col], b1 = bias[col + 1];
            if (r0 < M) {
                float2 v = make_float2(c[mt][nt][0] + b0, c[mt][nt][1] + b1);
                *reinterpret_cast<float2*>(C + (size_t)r0 * ldc + col) = v;
            }
            if (r1 < M) {
                float2 v = make_float2(c[mt][nt][2] + b0, c[mt][nt][3] + b1);
                *reinterpret_cast<float2*>(C + (size_t)r1 * ldc + col) = v;
            }
        }
    }
}

// gemm1 wrapper: cols [0,256) -> g_xl (ldc 256), cols [256,768) -> g_xri (ldc 512)
__global__ void __launch_bounds__(256, 2) k_mgemm1(const __nv_bfloat16* __restrict__ A,
                                                   const __nv_bfloat16* __restrict__ Bw,
                                                   const float* __restrict__ bias,
                                                   float* __restrict__ Cxl,
                                                   float* __restrict__ Cxri, int M) {
    extern __shared__ __align__(16) char smem[];
    const int tid = threadIdx.x, wid = tid >> 5, lane = tid & 31;
    const int mBase = blockIdx.y * 128;
    const int bx = blockIdx.x;
    float* C; int ldc, nBase;
    if (bx < 2) { C = Cxl; ldc = 256; nBase = bx * 128; }
    else        { C = Cxri; ldc = 512; nBase = (bx - 2) * 128; }
    const int nBaseW = bx * 128;
    const uint32_t sb = s2u(smem);
    const uint32_t sA[2] = {sb, sb + ABYTES};
    const uint32_t sB[2] = {sb + 2 * ABYTES, sb + 3 * ABYTES};

    const int wm = wid & 1;
    const int wn = wid >> 1;
    const int grp = lane >> 3;
    const int l8 = lane & 7;
    const int ldRow = tid >> 3;
    const int ldSeg = tid & 7;

    float c[4][4][4];
#pragma unroll
    for (int mt = 0; mt < 4; mt++)
#pragma unroll
        for (int nt = 0; nt < 4; nt++)
#pragma unroll
            for (int q = 0; q < 4; q++) c[mt][nt][q] = 0.0f;

    uint32_t aAddr[4];
#pragma unroll
    for (int mt = 0; mt < 4; mt++) {
        int row = wm * 64 + mt * 16 + (grp & 1) * 8 + l8;
        aAddr[mt] = (uint32_t)(row * (SSTRIDE * 2) + (grp >> 1) * 16);
    }
    uint32_t bAddr[2];
#pragma unroll
    for (int p = 0; p < 2; p++) {
        int nrow = wn * 32 + (2 * p + (grp >> 1)) * 8 + l8;
        bAddr[p] = (uint32_t)(nrow * (SSTRIDE * 2) + (grp & 1) * 16);
    }

    {
        const int b = 0, ch = 0;
#pragma unroll
        for (int i = 0; i < 4; i++) {
            int row = ldRow + i * 32;
            uint32_t sa = sA[b] + (uint32_t)(row * (SSTRIDE * 2) + ldSeg * 16);
            const __nv_bfloat16* ga = A + (size_t)(mBase + row) * KB + ch * 64 + ldSeg * 8;
            asm volatile("cp.async.cg.shared.global [%0], [%1], 16;" :: "r"(sa), "l"(ga));
            uint32_t sbb = sB[b] + (uint32_t)(row * (SSTRIDE * 2) + ldSeg * 16);
            const __nv_bfloat16* gb = Bw + (size_t)(nBaseW + row) * KB + ch * 64 + ldSeg * 8;
            asm volatile("cp.async.cg.shared.global [%0], [%1], 16;" :: "r"(sbb), "l"(gb));
        }
        asm volatile("cp.async.commit_group;" ::: "memory");
    }

    for (int ch = 0; ch < 12; ch++) {
        int b = ch & 1;
        if (ch + 1 < 12) {
            int nb = (ch + 1) & 1;
#pragma unroll
            for (int i = 0; i < 4; i++) {
                int row = ldRow + i * 32;
                uint32_t sa = sA[nb] + (uint32_t)(row * (SSTRIDE * 2) + ldSeg * 16);
                const __nv_bfloat16* ga = A + (size_t)(mBase + row) * KB + (ch + 1) * 64 + ldSeg * 8;
                asm volatile("cp.async.cg.shared.global [%0], [%1], 16;" :: "r"(sa), "l"(ga));
                uint32_t sbb = sB[nb] + (uint32_t)(row * (SSTRIDE * 2) + ldSeg * 16);
                const __nv_bfloat16* gb = Bw + (size_t)(nBaseW + row) * KB + (ch + 1) * 64 + ldSeg * 8;
                asm volatile("cp.async.cg.shared.global [%0], [%1], 16;" :: "r"(sbb), "l"(gb));
            }
            asm volatile("cp.async.commit_group;" ::: "memory");
            asm volatile("cp.async.wait_group 1;" ::: "memory");
        } else {
            asm volatile("cp.async.wait_group 0;" ::: "memory");
        }
        __syncthreads();

#pragma unroll
        for (int ks = 0; ks < 4; ks++) {
            uint32_t a[4][4], bb[4][2];
#pragma unroll
            for (int mt = 0; mt < 4; mt++) {
                uint32_t addr = sA[b] + aAddr[mt] + ks * 32;
                asm volatile("ldmatrix.sync.aligned.m8n8.x4.shared.b16 {%0,%1,%2,%3}, [%4];"
                             : "=r"(a[mt][0]), "=r"(a[mt][1]), "=r"(a[mt][2]), "=r"(a[mt][3])
                             : "r"(addr));
            }
#pragma unroll
            for (int p = 0; p < 2; p++) {
                uint32_t addr = sB[b] + bAddr[p] + ks * 32;
                asm volatile("ldmatrix.sync.aligned.m8n8.x4.shared.b16 {%0,%1,%2,%3}, [%4];"
                             : "=r"(bb[2 * p][0]), "=r"(bb[2 * p][1]),
                               "=r"(bb[2 * p + 1][0]), "=r"(bb[2 * p + 1][1])
                             : "r"(addr));
            }
#pragma unroll
            for (int mt = 0; mt < 4; mt++)
#pragma unroll
                for (int nt = 0; nt < 4; nt++) {
                    asm volatile(
                        "mma.sync.aligned.m16n8k16.row.col.f32.bf16.bf16.f32 "
                        "{%0,%1,%2,%3}, {%4,%5,%6,%7}, {%8,%9}, {%0,%1,%2,%3};"
                        : "+f"(c[mt][nt][0]), "+f"(c[mt][nt][1]),
                          "+f"(c[mt][nt][2]), "+f"(c[mt][nt][3])
                        : "r"(a[mt][0]), "r"(a[mt][1]), "r"(a[mt][2]), "r"(a[mt][3]),
                          "r"(bb[nt][0]), "r"(bb[nt][1]));
                }
        }
        __syncthreads();
    }

#pragma unroll
    for (int mt = 0; mt < 4; mt++) {
        int r0 = mBase + wm * 64 + mt * 16 + (lane >> 2);
        int r1 = r0 + 8;
#pragma unroll
        for (int nt = 0; nt < 4; nt++) {
            int colW = nBaseW + wn * 32 + nt * 8 + (lane & 3) * 2;
            int col = nBase + wn * 32 + nt * 8 + (lane & 3) * 2;
            float b0 = bias[colW], b1 = bias[colW + 1];
            if (r0 < M) {
                float2 v = make_float2(c[mt][nt][0] + b0, c[mt][nt][1] + b1);
                *reinterpret_cast<float2*>(C + (size_t)r0 * ldc + col) = v;
            }
            if (r1 < M) {
                float2 v = make_float2(c[mt][nt][2] + b0, c[mt][nt][3] + b1);
                *reinterpret_cast<float2*>(C + (size_t)r1 * ldc + col) = v;
            }
        }
    }
}

// ---------------- CSR build ----------------
__global__ void k_hist(const int* __restrict__ ei) {
    int t = blockIdx.x * blockDim.x + threadIdx.x;
    if (t < EE) atomicAdd(&g_deg[ei[EE + t]], 1);
}

__global__ void k_scan1() {
    __shared__ int sh[256];
    int b = blockIdx.x, tid = threadIdx.x;
    int i = b * 256 + tid;
    int v = (i < NN) ? g_deg[i] : 0;
    sh[tid] = v;
    __syncthreads();
    for (int o = 1; o < 256; o <<= 1) {
        int t = (tid >= o) ? sh[tid - o] : 0;
        __syncthreads();
        sh[tid] += t;
        __syncthreads();
    }
    if (i < NN) g_off[i] = sh[tid] - v;
    if (tid == 255) g_bsum[b] = sh[255];
}

__global__ void k_scan2() {
    __shared__ int sh[256];
    int tid = threadIdx.x;
    int v = (tid < 196) ? g_bsum[tid] : 0;
    sh[tid] = v;
    __syncthreads();
    for (int o = 1; o < 256; o <<= 1) {
        int t = (tid >= o) ? sh[tid - o] : 0;
        __syncthreads();
        sh[tid] += t;
        __syncthreads();
    }
    g_bsum[tid] = sh[tid] - v;
}

__global__ void k_scan3() {
    int i = blockIdx.x * 256 + threadIdx.x;
    if (i < NN) g_off[i] += g_bsum[blockIdx.x];
    if (i == 0) g_off[NN] = EE;
}

// bucket fill + geometry precompute + edge_attr output
__global__ void k_bucket(const int* __restrict__ ei, float* __restrict__ outE) {
    int t = blockIdx.x * blockDim.x + threadIdx.x;
    if (t < EE) {
        int s = ei[t];
        int d = ei[EE + t];
        int p = atomicAdd(&g_cur[d], 1);
        int pos = g_off[d] + p;
        g_bkt[pos] = t;
        const float2* nuv2 = (const float2*)g_nuv;
        float2 nd = nuv2[d], ns = nuv2[s];
        float rx = nd.x - ns.x;
        float ry = nd.y - ns.y;
        float dd = sqrtf(rx * rx + ry * ry);
        g_bgeo[pos] = make_float4(rx, ry, dd, __int_as_float(s));
        outE[(size_t)t * 3]     = rx;
        outE[(size_t)t * 3 + 1] = ry;
        outE[(size_t)t * 3 + 2] = dd;
    }
}

// ------- per-node attention: 2 warps/node, dual-state softmax, alpha, LN, SiLU -------
__global__ void __launch_bounds__(256) k_agg(const float* __restrict__ att,
                      const float* __restrict__ We, const float* __restrict__ cb,
                      const float* __restrict__ ng, const float* __restrict__ nb,
                      float* __restrict__ outA) {
    int gw = (blockIdx.x * blockDim.x + threadIdx.x) >> 5;
    int lane = threadIdx.x & 31;
    int wib = (threadIdx.x >> 5);
    int n = gw >> 1;
    int w = gw & 1;

    int fbase = w * 128 + lane * 4;
    float attv[4], we0[4], we1[4], we2[4], xr[4], accA[4], accB[4];
#pragma unroll
    for (int k = 0; k < 4; k++) {
        int j = fbase + k;
        attv[k] = att[j];
        we0[k] = We[j * 3]; we1[k] = We[j * 3 + 1]; we2[k] = We[j * 3 + 2];
        accA[k] = 0.0f; accB[k] = 0.0f;
    }
    {
        float4 a = ((const float4*)&g_xri[(size_t)n * 512 + w * 128])[lane];
        xr[0] = a.x; xr[1] = a.y; xr[2] = a.z; xr[3] = a.w;
    }
    float mA = -3.0e38f, sA = 0.0f, mB = -3.0e38f, sB = 0.0f;
    int beg = g_off[n], end = g_off[n + 1];
    int hsel = w * 2 + (lane >> 4);

    int i = beg;
    float4 gA = make_float4(0.f,0.f,0.f,0.f), gB = gA, xA = gA, xB = gA;
    if (i + 1 < end) {
        gA = g_bgeo[i]; gB = g_bgeo[i + 1];
        xA = ((const float4*)&g_xl[(size_t)__float_as_int(gA.w) * 256 + w * 128])[lane];
        xB = ((const float4*)&g_xl[(size_t)__float_as_int(gB.w) * 256 + w * 128])[lane];
    }
    while (i + 1 < end) {
        float4 cgA = gA, cgB = gB;
        float xlA[4] = {xA.x, xA.y, xA.z, xA.w};
        float xlB[4] = {xB.x, xB.y, xB.z, xB.w};
        int ni = i + 2;
        if (ni + 1 < end) {
            gA = g_bgeo[ni]; gB = g_bgeo[ni + 1];
            xA = ((const float4*)&g_xl[(size_t)__float_as_int(gA.w) * 256 + w * 128])[lane];
            xB = ((const float4*)&g_xl[(size_t)__float_as_int(gB.w) * 256 + w * 128])[lane];
        }
        float ppA = 0.0f, ppB = 0.0f;
#pragma unroll
        for (int k = 0; k < 4; k++) {
            float zA = xlA[k] + xr[k] + (cgA.x * we0[k] + cgA.y * we1[k] + cgA.z * we2[k]);
            float zB = xlB[k] + xr[k] + (cgB.x * we0[k] + cgB.y * we1[k] + cgB.z * we2[k]);
            zA = (zA > 0.0f) ? zA : 0.2f * zA;
            zB = (zB > 0.0f) ? zB : 0.2f * zB;
            ppA += zA * attv[k];
            ppB += zB * attv[k];
        }
#pragma unroll
        for (int o = 1; o < 16; o <<= 1) {
            ppA += __shfl_xor_sync(0xffffffffu, ppA, o);
            ppB += __shfl_xor_sync(0xffffffffu, ppB, o);
        }
        if ((lane & 15) == 0) {
            g_logits[i * 4 + hsel]       = ppA;
            g_logits[(i + 1) * 4 + hsel] = ppB;
        }
        {
            float mn = fmaxf(mA, ppA);
            float sc = __expf(mA - mn);
            float p = __expf(ppA - mn);
            sA = sA * sc + p;
            mA = mn;
#pragma unroll
            for (int k = 0; k < 4; k++) accA[k] = accA[k] * sc + p * xlA[k];
        }
        {
            float mn = fmaxf(mB, ppB);
            float sc = __expf(mB - mn);
            float p = __expf(ppB - mn);
            sB = sB * sc + p;
            mB = mn;
#pragma unroll
            for (int k = 0; k < 4; k++) accB[k] = accB[k] * sc + p * xlB[k];
        }
        i = ni;
    }
    if (i < end) {
        float4 g = g_bgeo[i];
        float4 xa = ((const float4*)&g_xl[(size_t)__float_as_int(g.w) * 256 + w * 128])[lane];
        float xl[4] = {xa.x, xa.y, xa.z, xa.w};
        float pp = 0.0f;
#pragma unroll
        for (int k = 0; k < 4; k++) {
            float z = xl[k] + xr[k] + (g.x * we0[k] + g.y * we1[k] + g.z * we2[k]);
            z = (z > 0.0f) ? z : 0.2f * z;
            pp += z * attv[k];
        }
#pragma unroll
        for (int o = 1; o < 16; o <<= 1) pp += __shfl_xor_sync(0xffffffffu, pp, o);
        if ((lane & 15) == 0) g_logits[i * 4 + hsel] = pp;
        float mn = fmaxf(mA, pp);
        float sc = __expf(mA - mn);
        float p = __expf(pp - mn);
        sA = sA * sc + p;
        mA = mn;
#pragma unroll
        for (int k = 0; k < 4; k++) accA[k] = accA[k] * sc + p * xl[k];
    }

    float m = fmaxf(mA, mB);
    float eA = __expf(mA - m), eB = __expf(mB - m);
    float s = sA * eA + sB * eB;
    float acc[4];
#pragma unroll
    for (int k = 0; k < 4; k++) acc[k] = accA[k] * eA + accB[k] * eB;

    __threadfence_block();
    __syncwarp();
    {
        float mh0 = __shfl_sync(0xffffffffu, m, 0);
        float mh1 = __shfl_sync(0xffffffffu, m, 16);
        float ih0 = 1.0f / (__shfl_sync(0xffffffffu, s, 0)  + 1e-16f);
        float ih1 = 1.0f / (__shfl_sync(0xffffffffu, s, 16) + 1e-16f);
        int deg = end - beg;
        for (int j = lane; j < deg; j += 32) {
            int pos = beg + j;
            float2 lg = *(const float2*)&g_logits[(size_t)pos * 4 + w * 2];
            int e = g_bkt[pos];
            float2 av;
            av.x = __expf(lg.x - mh0) * ih0;
            av.y = __expf(lg.y - mh1) * ih1;
            *(float2*)&outA[(size_t)e * 4 + w * 2] = av;
        }
    }

    float inv = (end > beg) ? (1.0f / s) : 0.0f;
    float o[4];
#pragma unroll
    for (int k = 0; k < 4; k++) o[k] = acc[k] * inv + cb[fbase + k];

    __shared__ float sSum[8], sVar[8];
    float ps = o[0] + o[1] + o[2] + o[3];
    ps = wsum(ps);
    if (lane == 0) sSum[wib] = ps;
    __syncthreads();
    float mean = (sSum[wib ^ 1] + ps) * (1.0f / 256.0f);
    float pv = 0.0f;
#pragma unroll
    for (int k = 0; k < 4; k++) { float d = o[k] - mean; pv += d * d; }
    pv = wsum(pv);
    if (lane == 0) sVar[wib] = pv;
    __syncthreads();
    float var = (sVar[wib ^ 1] + pv) * (1.0f / 256.0f);
    float r = rsqrtf(var + 1e-5f);

    float4 iv = ((const float4*)&g_xri[(size_t)n * 512 + 256 + w * 128])[lane];
    float idv[4] = {iv.x, iv.y, iv.z, iv.w};
    float y[4];
#pragma unroll
    for (int k = 0; k < 4; k++) {
        int j = fbase + k;
        float t = (o[k] - mean) * r * ng[j] + nb[j] + idv[k];
        y[k] = t / (1.0f + __expf(-t));
    }
    float rl[4];
    uint2 hiv, lov;
    hiv.x = pk2(y[0], y[1], &rl[0], &rl[1]);
    hiv.y = pk2(y[2], y[3], &rl[2], &rl[3]);
    lov.x = pk2n(rl[0], rl[1]);
    lov.y = pk2n(rl[2], rl[3]);
    size_t base = (size_t)n * KB + fbase;
    *reinterpret_cast<uint2*>(&g_Abig[base])       = hiv;
    *reinterpret_cast<uint2*>(&g_Abig[base + 256]) = hiv;
    *reinterpret_cast<uint2*>(&g_Abig[base + 512]) = lov;
}

// ---------------- host launcher ----------------
extern "C" void kernel_launch(void* const* d_in, const int* in_sizes, int n_in,
                              void* d_out, int out_size) {
    const float* x      = (const float*)d_in[0];
    const float* kpts   = (const float*)d_in[1];
    const float* pts3d  = (const float*)d_in[2];
    const float* pe_w1  = (const float*)d_in[3];
    const float* pe_b1  = (const float*)d_in[4];
    const float* pe_g1  = (const float*)d_in[5];
    const float* pe_bn1 = (const float*)d_in[6];
    const float* pe_w2  = (const float*)d_in[7];
    const float* pe_b2  = (const float*)d_in[8];
    const float* pe_g2  = (const float*)d_in[9];
    const float* pe_bn2 = (const float*)d_in[10];
    const float* lin_l_w = (const float*)d_in[11];
    const float* lin_l_b = (const float*)d_in[12];
    const float* lin_r_w = (const float*)d_in[13];
    const float* lin_r_b = (const float*)d_in[14];
    const float* lin_edge_w = (const float*)d_in[15];
    const float* att    = (const float*)d_in[16];
    const float* conv_b = (const float*)d_in[17];
    const float* norm_g = (const float*)d_in[18];
    const float* norm_b = (const float*)d_in[19];
    const float* res_w  = (const float*)d_in[20];
    const float* res_b  = (const float*)d_in[21];
    const float* proj_w = (const float*)d_in[22];
    const float* proj_b = (const float*)d_in[23];
    const int*   ei     = (const int*)d_in[24];
    float* out = (float*)d_out;

    static cudaStream_t s1 = nullptr;
    static cudaEvent_t evFork0 = nullptr, evC = nullptr, evNode = nullptr, evJoin = nullptr;
    if (!s1) {
        cudaStreamCreateWithFlags(&s1, cudaStreamNonBlocking);
        cudaEventCreateWithFlags(&evFork0, cudaEventDisableTiming);
        cudaEventCreateWithFlags(&evC, cudaEventDisableTiming);
        cudaEventCreateWithFlags(&evNode, cudaEventDisableTiming);
        cudaEventCreateWithFlags(&evJoin, cudaEventDisableTiming);
        cudaFuncSetAttribute(k_mgemm, cudaFuncAttributeMaxDynamicSharedMemorySize, 4 * ABYTES);
        cudaFuncSetAttribute(k_mgemm1, cudaFuncAttributeMaxDynamicSharedMemorySize, 4 * ABYTES);
    }

    __nv_bfloat16* dA;  cudaGetSymbolAddress((void**)&dA,  g_Abig);
    __nv_bfloat16* dW;  cudaGetSymbolAddress((void**)&dW,  g_Wbig);
    __nv_bfloat16* dW2; cudaGetSymbolAddress((void**)&dW2, g_W2big);
    float* dB;    cudaGetSymbolAddress((void**)&dB,   g_B);
    float* dXL;   cudaGetSymbolAddress((void**)&dXL,  g_xl);
    float* dXRI;  cudaGetSymbolAddress((void**)&dXRI, g_xri);

    // fork side stream at entry; concat (gemm1 weights) runs concurrently with node prep
    cudaEventRecord(evFork0, 0);
    cudaStreamWaitEvent(s1, evFork0, 0);
    k_concat<<<768, 256, 0, s1>>>(lin_l_w, lin_r_w, res_w, lin_l_b, lin_r_b, res_b);
    cudaEventRecord(evC, s1);

    k_splitW2<<<256, 256>>>(proj_w, pe_w2);
    k_init<<<(NN + 255) / 256, 256>>>();
    k_node<<<(NN + 7) / 8, 256>>>(x, kpts, pts3d, pe_w1, pe_b1, pe_g1, pe_bn1,
                                  pe_b2, pe_g2, pe_bn2);
    cudaEventRecord(evNode, 0);

    // side stream: CSR chain + bucket, all hidden under gemm1
    cudaStreamWaitEvent(s1, evNode, 0);
    k_hist<<<(EE + 255) / 256, 256, 0, s1>>>(ei);
    k_scan1<<<196, 256, 0, s1>>>();
    k_scan2<<<1, 256, 0, s1>>>();
    k_scan3<<<196, 256, 0, s1>>>();
    k_bucket<<<(EE + 255) / 256, 256, 0, s1>>>(ei, out + NN * 256 + EE * 4);
    cudaEventRecord(evJoin, s1);

    // gemm1 (merged): x_l -> g_xl, x_r|identity -> g_xri
    cudaStreamWaitEvent(0, evC, 0);
    k_mgemm1<<<dim3(6, 391), 256, 4 * ABYTES>>>(dA, dW, dB, dXL, dXRI, NN);

    cudaStreamWaitEvent(0, evJoin, 0);
    k_agg<<<12500, 256>>>(att, lin_edge_w, conv_b, norm_g, norm_b,
                          out + NN * 256);

    // gemm2: final projection
    k_mgemm<<<dim3(2, 391), 256, 4 * ABYTES>>>(dA, dW2, proj_b, out, NN, 256);
}